// round 2
// baseline (speedup 1.0000x reference)
#include <cuda_runtime.h>
#include <math.h>

// Problem-fixed capacities (dataset constants)
#define NCAP 100000
#define ECAP 1600000
#define ITERS 5

struct __align__(8) EdgeRec { int src; float w; };

// ---- static device scratch (no allocation allowed) ----
__device__ int     g_counts[NCAP];
__device__ int     g_rowoff[NCAP + 1];
__device__ int     g_bsums[1024];
__device__ float   g_dis[NCAP];
__device__ EdgeRec g_edges[ECAP];
__device__ float   g_aggx[NCAP * 3];
// float4-typed to guarantee 16B alignment for vector loads
__device__ float4  g_t[NCAP * 16];
__device__ float4  g_u[NCAP * 16];
__device__ float4  g_v[NCAP * 16];

// =============== graph setup kernels ===============

__global__ void k_count(const int* __restrict__ dst, int E, int* __restrict__ counts) {
    int i = blockIdx.x * blockDim.x + threadIdx.x;
    if (i < E) atomicAdd(&counts[dst[i]], 1);
}

__global__ void k_dis(const int* __restrict__ counts, float* __restrict__ dis, int N) {
    int i = blockIdx.x * blockDim.x + threadIdx.x;
    if (i < N) dis[i] = rsqrtf((float)(counts[i] + 1));   // +1 self loop, deg >= 1
}

// exclusive scan of counts -> rowoff, 3-phase
__global__ void k_scan1(const int* __restrict__ counts, int* __restrict__ out,
                        int* __restrict__ bsums, int n) {
    __shared__ int s[512];
    int tid = threadIdx.x;
    int i = blockIdx.x * 512 + tid;
    int v = (i < n) ? counts[i] : 0;
    s[tid] = v;
    __syncthreads();
    for (int off = 1; off < 512; off <<= 1) {
        int t = 0;
        if (tid >= off) t = s[tid - off];
        __syncthreads();
        s[tid] += t;
        __syncthreads();
    }
    if (i < n) out[i] = s[tid] - v;           // exclusive
    if (tid == 511) bsums[blockIdx.x] = s[511];
}

__global__ void k_scan2(int* __restrict__ bsums, int nb) {
    __shared__ int s[256];
    int tid = threadIdx.x;
    int v = (tid < nb) ? bsums[tid] : 0;
    s[tid] = v;
    __syncthreads();
    for (int off = 1; off < 256; off <<= 1) {
        int t = 0;
        if (tid >= off) t = s[tid - off];
        __syncthreads();
        s[tid] += t;
        __syncthreads();
    }
    if (tid < nb) bsums[tid] = s[tid] - v;    // exclusive block offsets
}

__global__ void k_scan3(int* __restrict__ out, const int* __restrict__ bsums, int n, int E) {
    int i = blockIdx.x * 512 + threadIdx.x;
    if (i < n) out[i] += bsums[blockIdx.x];
    if (i == 0) out[n] = E;
}

__global__ void k_fill(const int* __restrict__ srcA, const int* __restrict__ dstA, int E,
                       const int* __restrict__ rowoff, int* __restrict__ cursor,
                       const float* __restrict__ dis, EdgeRec* __restrict__ edges) {
    int i = blockIdx.x * blockDim.x + threadIdx.x;
    if (i >= E) return;
    int s = srcA[i], d = dstA[i];
    int pos = rowoff[d] + atomicAdd(&cursor[d], 1);
    EdgeRec r;
    r.src = s;
    r.w = dis[s] * dis[d];
    edges[pos] = r;
}

// =============== FUSED agg + matmul layer ===============
// out[N,64] = epilogue( agg(Hin)[N,64] @ W[64,64] )
// epilogue: + bias[64]  (+ aggx@Wx if RECALL)  (+ res if RES)  (relu if RELU)
// Tile: 96 nodes per block, 96 threads. Phase 1: 3 warps gather 32 nodes each
// into smem. Phase 2: register-blocked 8x8 matmul (identical to mm96).
template <int RECALL, int RES, int RELU>
__global__ void __launch_bounds__(96) k_fused(
    const float* __restrict__ Hin, const EdgeRec* __restrict__ edges,
    const int* __restrict__ rowoff, const float* __restrict__ dis,
    const float* __restrict__ W, const float* __restrict__ bias,
    const float* __restrict__ res,
    const float* __restrict__ aggx, const float* __restrict__ Wx,
    float* __restrict__ out, int N) {
    __shared__ float As[96][65];
    __shared__ float Ws[64][64];
    int tid = threadIdx.x;
    int row0 = blockIdx.x * 96;
    int lane = tid & 31;
    int warp = tid >> 5;   // 0..2

    // load W (independent of gather)
    {
        const float4* Wv = (const float4*)W;
        float4* Wsv = (float4*)Ws;
        for (int i = tid; i < 1024; i += 96) Wsv[i] = Wv[i];
    }

    // ---- phase 1: aggregate 32 nodes per warp into As ----
    const float2* U = (const float2*)Hin;
    for (int s = 0; s < 32; s++) {
        int r = warp * 32 + s;
        int node = row0 + r;
        float2 a0 = make_float2(0.f, 0.f), a1 = a0, a2 = a0, a3 = a0;
        if (node < N) {
            int e0 = rowoff[node], e1 = rowoff[node + 1];
            int e = e0;
            for (; e + 4 <= e1; e += 4) {
                EdgeRec r0 = edges[e], r1 = edges[e + 1];
                EdgeRec r2 = edges[e + 2], r3 = edges[e + 3];
                float2 f0 = U[(size_t)r0.src * 32 + lane];
                float2 f1 = U[(size_t)r1.src * 32 + lane];
                float2 f2 = U[(size_t)r2.src * 32 + lane];
                float2 f3 = U[(size_t)r3.src * 32 + lane];
                a0.x = fmaf(r0.w, f0.x, a0.x); a0.y = fmaf(r0.w, f0.y, a0.y);
                a1.x = fmaf(r1.w, f1.x, a1.x); a1.y = fmaf(r1.w, f1.y, a1.y);
                a2.x = fmaf(r2.w, f2.x, a2.x); a2.y = fmaf(r2.w, f2.y, a2.y);
                a3.x = fmaf(r3.w, f3.x, a3.x); a3.y = fmaf(r3.w, f3.y, a3.y);
            }
            for (; e < e1; e++) {
                EdgeRec rr = edges[e];
                float2 f = U[(size_t)rr.src * 32 + lane];
                a0.x = fmaf(rr.w, f.x, a0.x); a0.y = fmaf(rr.w, f.y, a0.y);
            }
            float dv = dis[node];
            float sw = dv * dv;
            float2 fs = U[(size_t)node * 32 + lane];
            a1.x = fmaf(sw, fs.x, a1.x); a1.y = fmaf(sw, fs.y, a1.y);
        }
        a0.x += a1.x + a2.x + a3.x;
        a0.y += a1.y + a2.y + a3.y;
        As[r][2 * lane]     = a0.x;
        As[r][2 * lane + 1] = a0.y;
    }
    __syncthreads();

    // ---- phase 2: matmul from smem ----
    int tx = tid & 7, ty = tid >> 3;
    float acc[8][8];
#pragma unroll
    for (int i = 0; i < 8; i++)
#pragma unroll
        for (int j = 0; j < 8; j++) acc[i][j] = 0.f;

#pragma unroll 8
    for (int k = 0; k < 64; k++) {
        float a[8];
#pragma unroll
        for (int i = 0; i < 8; i++) a[i] = As[ty * 8 + i][k];
        float4 w0 = *(const float4*)&Ws[k][tx * 8];
        float4 w1 = *(const float4*)&Ws[k][tx * 8 + 4];
        float wv[8] = {w0.x, w0.y, w0.z, w0.w, w1.x, w1.y, w1.z, w1.w};
#pragma unroll
        for (int i = 0; i < 8; i++)
#pragma unroll
            for (int j = 0; j < 8; j++) acc[i][j] = fmaf(a[i], wv[j], acc[i][j]);
    }

    // ---- epilogue ----
    float brr[8];
    float wxr[3][8];
#pragma unroll
    for (int j = 0; j < 8; j++) brr[j] = bias[tx * 8 + j];
    if (RECALL) {
#pragma unroll
        for (int j = 0; j < 8; j++) {
            int col = tx * 8 + j;
            wxr[0][j] = Wx[col];
            wxr[1][j] = Wx[64 + col];
            wxr[2][j] = Wx[128 + col];
        }
    }
#pragma unroll
    for (int i = 0; i < 8; i++) {
        int row = row0 + ty * 8 + i;
        if (row >= N) continue;
#pragma unroll
        for (int j = 0; j < 8; j++) acc[i][j] += brr[j];
        if (RECALL) {
            float a0 = aggx[row * 3], a1 = aggx[row * 3 + 1], a2 = aggx[row * 3 + 2];
#pragma unroll
            for (int j = 0; j < 8; j++)
                acc[i][j] += fmaf(a0, wxr[0][j], fmaf(a1, wxr[1][j], a2 * wxr[2][j]));
        }
        if (RES) {
            float4 r0 = ((const float4*)res)[(size_t)row * 16 + tx * 2];
            float4 r1 = ((const float4*)res)[(size_t)row * 16 + tx * 2 + 1];
            acc[i][0] += r0.x; acc[i][1] += r0.y; acc[i][2] += r0.z; acc[i][3] += r0.w;
            acc[i][4] += r1.x; acc[i][5] += r1.y; acc[i][6] += r1.z; acc[i][7] += r1.w;
        }
        if (RELU) {
#pragma unroll
            for (int j = 0; j < 8; j++) acc[i][j] = fmaxf(acc[i][j], 0.f);
        }
        float4 o0 = make_float4(acc[i][0], acc[i][1], acc[i][2], acc[i][3]);
        float4 o1 = make_float4(acc[i][4], acc[i][5], acc[i][6], acc[i][7]);
        ((float4*)out)[(size_t)row * 16 + tx * 2 + 0] = o0;
        ((float4*)out)[(size_t)row * 16 + tx * 2 + 1] = o1;
    }
}

// =============== head aggregation kernels ===============

// width-32: warp per node
__global__ void k_agg32(const float* __restrict__ u, const EdgeRec* __restrict__ edges,
                        const int* __restrict__ rowoff, const float* __restrict__ dis,
                        const float* __restrict__ bias, int relu,
                        float* __restrict__ out, int N) {
    int node = blockIdx.x * 8 + (threadIdx.x >> 5);
    int lane = threadIdx.x & 31;
    if (node >= N) return;
    float acc = 0.f;
    int e0 = rowoff[node], e1 = rowoff[node + 1];
    for (int e = e0; e < e1; e++) {
        EdgeRec r = edges[e];
        acc = fmaf(r.w, u[(size_t)r.src * 32 + lane], acc);
    }
    float dv = dis[node];
    acc = fmaf(dv * dv, u[(size_t)node * 32 + lane], acc);
    if (bias) acc += bias[lane];
    if (relu) acc = fmaxf(acc, 0.f);
    out[(size_t)node * 32 + lane] = acc;
}

// small widths (2,3,8): thread per node
template <int W>
__global__ void k_agg_t(const float* __restrict__ u, const EdgeRec* __restrict__ edges,
                        const int* __restrict__ rowoff, const float* __restrict__ dis,
                        const float* __restrict__ bias, int relu,
                        float* __restrict__ out, int N) {
    int node = blockIdx.x * blockDim.x + threadIdx.x;
    if (node >= N) return;
    float acc[W];
#pragma unroll
    for (int k = 0; k < W; k++) acc[k] = 0.f;
    int e0 = rowoff[node], e1 = rowoff[node + 1];
    for (int e = e0; e < e1; e++) {
        EdgeRec r = edges[e];
        const float* up = u + (size_t)r.src * W;
#pragma unroll
        for (int k = 0; k < W; k++) acc[k] = fmaf(r.w, __ldg(up + k), acc[k]);
    }
    float dv = dis[node];
    float sw = dv * dv;
    const float* us = u + (size_t)node * W;
#pragma unroll
    for (int k = 0; k < W; k++) acc[k] = fmaf(sw, us[k], acc[k]);
    if (bias) {
#pragma unroll
        for (int k = 0; k < W; k++) acc[k] += bias[k];
    }
    if (relu) {
#pragma unroll
        for (int k = 0; k < W; k++) acc[k] = fmaxf(acc[k], 0.f);
    }
#pragma unroll
    for (int k = 0; k < W; k++) out[(size_t)node * W + k] = acc[k];
}

// =============== small dense kernels ===============

// projection: t = relu(aggx @ Wp + bp), Wp [3,64]
__global__ void k_proj(const float* __restrict__ aggx, const float* __restrict__ Wp,
                       const float* __restrict__ bp, float* __restrict__ t, int N) {
    int node = blockIdx.x * 4 + (threadIdx.x >> 6);
    int j = threadIdx.x & 63;
    if (node >= N) return;
    float a0 = aggx[node * 3], a1 = aggx[node * 3 + 1], a2 = aggx[node * 3 + 2];
    float acc = bp[j];
    acc = fmaf(a0, Wp[j], acc);
    acc = fmaf(a1, Wp[64 + j], acc);
    acc = fmaf(a2, Wp[128 + j], acc);
    t[(size_t)node * 64 + j] = fmaxf(acc, 0.f);
}

// small head matmuls: warp per node
template <int FIN, int FOUT>
__global__ void k_mm_small(const float* __restrict__ A, const float* __restrict__ W,
                           float* __restrict__ C, int N) {
    __shared__ float Ws[FIN * FOUT + 32];
    int tid = threadIdx.x;
    for (int i = tid; i < FIN * FOUT; i += blockDim.x) Ws[i] = W[i];
    for (int i = FIN * FOUT + tid; i < FIN * FOUT + 32; i += blockDim.x) Ws[i] = 0.f;
    __syncthreads();
    int node = blockIdx.x * 4 + (tid >> 5);
    int j = tid & 31;
    if (node >= N) return;
    float acc = 0.f;
    const float* a = A + (size_t)node * FIN;
#pragma unroll
    for (int k = 0; k < FIN; k++) {
        float av = __ldg(a + k);
        acc = fmaf(av, Ws[k * FOUT + j], acc);
    }
    if (j < FOUT) C[(size_t)node * FOUT + j] = acc;
}

// =============== host launch ===============

extern "C" void kernel_launch(void* const* d_in, const int* in_sizes, int n_in,
                              void* d_out, int out_size) {
    const float* x   = (const float*)d_in[0];
    const float* Wp  = (const float*)d_in[1];
    const float* bp  = (const float*)d_in[2];
    const float* Wr  = (const float*)d_in[3];
    const float* br  = (const float*)d_in[4];
    const float* W11 = (const float*)d_in[5];
    const float* b11 = (const float*)d_in[6];
    const float* W12 = (const float*)d_in[7];
    const float* b12 = (const float*)d_in[8];
    const float* W21 = (const float*)d_in[9];
    const float* b21 = (const float*)d_in[10];
    const float* W22 = (const float*)d_in[11];
    const float* b22 = (const float*)d_in[12];
    const float* Wh1 = (const float*)d_in[13];
    const float* bh1 = (const float*)d_in[14];
    const float* Wh2 = (const float*)d_in[15];
    const float* bh2 = (const float*)d_in[16];
    const float* Wh3 = (const float*)d_in[17];
    const float* bh3 = (const float*)d_in[18];
    const int*   ei  = (const int*)d_in[19];

    int N = in_sizes[0] / 3;
    int E = in_sizes[19] / 2;
    const int* esrc = ei;
    const int* edst = ei + E;

    int *counts, *rowoff, *bsums;
    float *dis, *aggx;
    EdgeRec* edges;
    float4 *t4, *u4, *v4;
    cudaGetSymbolAddress((void**)&counts, g_counts);
    cudaGetSymbolAddress((void**)&rowoff, g_rowoff);
    cudaGetSymbolAddress((void**)&bsums, g_bsums);
    cudaGetSymbolAddress((void**)&dis, g_dis);
    cudaGetSymbolAddress((void**)&edges, g_edges);
    cudaGetSymbolAddress((void**)&aggx, g_aggx);
    cudaGetSymbolAddress((void**)&t4, g_t);
    cudaGetSymbolAddress((void**)&u4, g_u);
    cudaGetSymbolAddress((void**)&v4, g_v);
    float* t = (float*)t4;
    float* u = (float*)u4;
    float* v = (float*)v4;

    int nbE = (E + 255) / 256;
    int nbN = (N + 255) / 256;
    int nbScan = (N + 511) / 512;
    int nbWarp = (N + 7) / 8;
    int nbMM = (N + 95) / 96;
    int nbW4 = (N + 3) / 4;

    // ---- graph setup ----
    cudaMemsetAsync(counts, 0, (size_t)N * sizeof(int), 0);
    k_count<<<nbE, 256>>>(edst, E, counts);
    k_dis<<<nbN, 256>>>(counts, dis, N);
    k_scan1<<<nbScan, 512>>>(counts, rowoff, bsums, N);
    k_scan2<<<1, 256>>>(bsums, nbScan);
    k_scan3<<<nbScan, 512>>>(rowoff, bsums, N, E);
    cudaMemsetAsync(counts, 0, (size_t)N * sizeof(int), 0);
    k_fill<<<nbE, 256>>>(esrc, edst, E, rowoff, counts, dis, edges);

    // ---- loop-invariant: agg(x) and projection ----
    k_agg_t<3><<<nbN, 256>>>(x, edges, rowoff, dis, nullptr, 0, aggx, N);
    k_proj<<<nbW4, 256>>>(aggx, Wp, bp, t, N);

    const float* Wrx = Wr + 64 * 64;  // rows 64..66 of Wr (x part)

    // ---- iterations: each gcn = one fused agg+mm kernel ----
    float* cur = t;
    float* A = u;
    float* B = v;
    for (int it = 0; it < ITERS; it++) {
        // recall: A = agg(cur)@Wr_t + aggx@Wr_x + br
        k_fused<1, 0, 0><<<nbMM, 96>>>(cur, edges, rowoff, dis, Wr, br,
                                       nullptr, aggx, Wrx, A, N);
        // block 1
        k_fused<0, 0, 1><<<nbMM, 96>>>(A, edges, rowoff, dis, W11, b11,
                                       nullptr, nullptr, nullptr, B, N);
        k_fused<0, 1, 1><<<nbMM, 96>>>(B, edges, rowoff, dis, W12, b12,
                                       A, nullptr, nullptr, cur, N);
        // block 2
        k_fused<0, 0, 1><<<nbMM, 96>>>(cur, edges, rowoff, dis, W21, b21,
                                       nullptr, nullptr, nullptr, B, N);
        k_fused<0, 1, 1><<<nbMM, 96>>>(B, edges, rowoff, dis, W22, b22,
                                       cur, nullptr, nullptr, A, N);
        // state now in A; swap
        float* tmp = cur; cur = A; A = tmp;
    }

    // ---- head ----
    k_mm_small<64, 32><<<nbW4, 128>>>(cur, Wh1, u == cur ? v : u, N);
    float* h1 = (u == cur) ? v : u;
    float* h2 = (t == cur) ? ((u == cur) ? v : ((v == h1) ? u : v)) : t;
    // pick h2 as any buffer distinct from cur and h1:
    if (h2 == cur || h2 == h1) h2 = (t != cur && t != h1) ? t : ((u != cur && u != h1) ? u : v);
    k_agg32<<<nbWarp, 256>>>(h1, edges, rowoff, dis, bh1, 1, h2, N);
    k_mm_small<32, 8><<<nbW4, 128>>>(h2, Wh2, h1, N);
    k_agg_t<8><<<nbN, 256>>>(h1, edges, rowoff, dis, bh2, 1, h2, N);
    k_mm_small<8, 2><<<nbW4, 128>>>(h2, Wh3, h1, N);
    k_agg_t<2><<<nbN, 256>>>(h1, edges, rowoff, dis, bh3, 0, (float*)d_out, N);
}

// round 5
// speedup vs baseline: 2.2975x; 2.2975x over previous
#include <cuda_runtime.h>
#include <math.h>

// Problem-fixed capacities (dataset constants)
#define NCAP 100000
#define ECAP 1600000
#define ITERS 5

struct __align__(8) EdgeRec { int src; float w; };
typedef unsigned long long u64;

// ---- static device scratch (no allocation allowed) ----
__device__ int     g_counts[NCAP];
__device__ int     g_rowoff[NCAP + 1];
__device__ int     g_bsums[1024];
__device__ float   g_dis[NCAP];
__device__ EdgeRec g_edges[ECAP];
__device__ float   g_aggx[NCAP * 3];
// float4-typed to guarantee 16B alignment for vector loads
__device__ float4  g_t[NCAP * 16];
__device__ float4  g_u[NCAP * 16];
__device__ float4  g_v[NCAP * 16];

// ---- packed fp32x2 helpers (Blackwell FFMA2 path) ----
__device__ __forceinline__ u64 pack2(float x, float y) {
    u64 r; asm("mov.b64 %0, {%1, %2};" : "=l"(r) : "f"(x), "f"(y)); return r;
}
__device__ __forceinline__ void unpack2(u64 v, float& x, float& y) {
    asm("mov.b64 {%0, %1}, %2;" : "=f"(x), "=f"(y) : "l"(v));
}
__device__ __forceinline__ void ffma2(u64& d, u64 a, u64 b) {
    asm("fma.rn.f32x2 %0, %1, %2, %0;" : "+l"(d) : "l"(a), "l"(b));
}

// =============== graph setup kernels ===============

__global__ void k_count(const int* __restrict__ dst, int E, int* __restrict__ counts) {
    int i = blockIdx.x * blockDim.x + threadIdx.x;
    if (i < E) atomicAdd(&counts[dst[i]], 1);
}

__global__ void k_dis(const int* __restrict__ counts, float* __restrict__ dis, int N) {
    int i = blockIdx.x * blockDim.x + threadIdx.x;
    if (i < N) dis[i] = rsqrtf((float)(counts[i] + 1));   // +1 self loop
}

// exclusive scan of counts -> rowoff, 3-phase
__global__ void k_scan1(const int* __restrict__ counts, int* __restrict__ out,
                        int* __restrict__ bsums, int n) {
    __shared__ int s[512];
    int tid = threadIdx.x;
    int i = blockIdx.x * 512 + tid;
    int v = (i < n) ? counts[i] : 0;
    s[tid] = v;
    __syncthreads();
    for (int off = 1; off < 512; off <<= 1) {
        int t = 0;
        if (tid >= off) t = s[tid - off];
        __syncthreads();
        s[tid] += t;
        __syncthreads();
    }
    if (i < n) out[i] = s[tid] - v;           // exclusive
    if (tid == 511) bsums[blockIdx.x] = s[511];
}

__global__ void k_scan2(int* __restrict__ bsums, int nb) {
    __shared__ int s[256];
    int tid = threadIdx.x;
    int v = (tid < nb) ? bsums[tid] : 0;
    s[tid] = v;
    __syncthreads();
    for (int off = 1; off < 256; off <<= 1) {
        int t = 0;
        if (tid >= off) t = s[tid - off];
        __syncthreads();
        s[tid] += t;
        __syncthreads();
    }
    if (tid < nb) bsums[tid] = s[tid] - v;
}

__global__ void k_scan3(int* __restrict__ out, const int* __restrict__ bsums, int n, int E) {
    int i = blockIdx.x * 512 + threadIdx.x;
    if (i < n) out[i] += bsums[blockIdx.x];
    if (i == 0) out[n] = E;
}

__global__ void k_fill(const int* __restrict__ srcA, const int* __restrict__ dstA, int E,
                       const int* __restrict__ rowoff, int* __restrict__ cursor,
                       const float* __restrict__ dis, EdgeRec* __restrict__ edges) {
    int i = blockIdx.x * blockDim.x + threadIdx.x;
    if (i >= E) return;
    int s = srcA[i], d = dstA[i];
    int pos = rowoff[d] + atomicAdd(&cursor[d], 1);
    EdgeRec r;
    r.src = s;
    r.w = dis[s] * dis[d];
    edges[pos] = r;
}

// =============== aggregation kernels ===============

// width-64: warp per node, float2 per lane, 4-way unrolled edge loop
__global__ void k_agg64(const float* __restrict__ u, const EdgeRec* __restrict__ edges,
                        const int* __restrict__ rowoff, const float* __restrict__ dis,
                        const float* __restrict__ bias, const float* __restrict__ res,
                        int relu, float* __restrict__ out, int N) {
    int node = blockIdx.x * 8 + (threadIdx.x >> 5);
    int lane = threadIdx.x & 31;
    if (node >= N) return;
    const float2* U = (const float2*)u;
    float2 a0 = make_float2(0.f, 0.f), a1 = a0, a2 = a0, a3 = a0;
    int e0 = rowoff[node], e1 = rowoff[node + 1];
    int e = e0;
    for (; e + 4 <= e1; e += 4) {
        EdgeRec r0 = edges[e],     r1 = edges[e + 1];
        EdgeRec r2 = edges[e + 2], r3 = edges[e + 3];
        float2 f0 = U[(size_t)r0.src * 32 + lane];
        float2 f1 = U[(size_t)r1.src * 32 + lane];
        float2 f2 = U[(size_t)r2.src * 32 + lane];
        float2 f3 = U[(size_t)r3.src * 32 + lane];
        a0.x = fmaf(r0.w, f0.x, a0.x); a0.y = fmaf(r0.w, f0.y, a0.y);
        a1.x = fmaf(r1.w, f1.x, a1.x); a1.y = fmaf(r1.w, f1.y, a1.y);
        a2.x = fmaf(r2.w, f2.x, a2.x); a2.y = fmaf(r2.w, f2.y, a2.y);
        a3.x = fmaf(r3.w, f3.x, a3.x); a3.y = fmaf(r3.w, f3.y, a3.y);
    }
    for (; e < e1; e++) {
        EdgeRec rr = edges[e];
        float2 f = U[(size_t)rr.src * 32 + lane];
        a0.x = fmaf(rr.w, f.x, a0.x); a0.y = fmaf(rr.w, f.y, a0.y);
    }
    float dv = dis[node];
    float sw = dv * dv;
    float2 fs = U[(size_t)node * 32 + lane];
    a1.x = fmaf(sw, fs.x, a1.x); a1.y = fmaf(sw, fs.y, a1.y);
    float2 acc;
    acc.x = (a0.x + a1.x) + (a2.x + a3.x);
    acc.y = (a0.y + a1.y) + (a2.y + a3.y);
    if (bias) {
        float2 b = ((const float2*)bias)[lane];
        acc.x += b.x; acc.y += b.y;
    }
    if (res) {
        float2 rr = ((const float2*)res)[(size_t)node * 32 + lane];
        acc.x += rr.x; acc.y += rr.y;
    }
    if (relu) {
        acc.x = fmaxf(acc.x, 0.f);
        acc.y = fmaxf(acc.y, 0.f);
    }
    ((float2*)out)[(size_t)node * 32 + lane] = acc;
}

// width-32: warp per node, 1 float per lane
__global__ void k_agg32(const float* __restrict__ u, const EdgeRec* __restrict__ edges,
                        const int* __restrict__ rowoff, const float* __restrict__ dis,
                        const float* __restrict__ bias, int relu,
                        float* __restrict__ out, int N) {
    int node = blockIdx.x * 8 + (threadIdx.x >> 5);
    int lane = threadIdx.x & 31;
    if (node >= N) return;
    float acc = 0.f;
    int e0 = rowoff[node], e1 = rowoff[node + 1];
    for (int e = e0; e < e1; e++) {
        EdgeRec r = edges[e];
        acc = fmaf(r.w, u[(size_t)r.src * 32 + lane], acc);
    }
    float dv = dis[node];
    acc = fmaf(dv * dv, u[(size_t)node * 32 + lane], acc);
    if (bias) acc += bias[lane];
    if (relu) acc = fmaxf(acc, 0.f);
    out[(size_t)node * 32 + lane] = acc;
}

// small widths (2,3,8): thread per node
template <int W>
__global__ void k_agg_t(const float* __restrict__ u, const EdgeRec* __restrict__ edges,
                        const int* __restrict__ rowoff, const float* __restrict__ dis,
                        const float* __restrict__ bias, int relu,
                        float* __restrict__ out, int N) {
    int node = blockIdx.x * blockDim.x + threadIdx.x;
    if (node >= N) return;
    float acc[W];
#pragma unroll
    for (int k = 0; k < W; k++) acc[k] = 0.f;
    int e0 = rowoff[node], e1 = rowoff[node + 1];
    for (int e = e0; e < e1; e++) {
        EdgeRec r = edges[e];
        const float* up = u + (size_t)r.src * W;
#pragma unroll
        for (int k = 0; k < W; k++) acc[k] = fmaf(r.w, __ldg(up + k), acc[k]);
    }
    float dv = dis[node];
    float sw = dv * dv;
    const float* us = u + (size_t)node * W;
#pragma unroll
    for (int k = 0; k < W; k++) acc[k] = fmaf(sw, us[k], acc[k]);
    if (bias) {
#pragma unroll
        for (int k = 0; k < W; k++) acc[k] += bias[k];
    }
    if (relu) {
#pragma unroll
        for (int k = 0; k < W; k++) acc[k] = fmaxf(acc[k], 0.f);
    }
#pragma unroll
    for (int k = 0; k < W; k++) out[(size_t)node * W + k] = acc[k];
}

// =============== dense kernels ===============

// projection: t = relu(aggx @ Wp + bp), Wp [3,64]
__global__ void k_proj(const float* __restrict__ aggx, const float* __restrict__ Wp,
                       const float* __restrict__ bp, float* __restrict__ t, int N) {
    int node = blockIdx.x * 4 + (threadIdx.x >> 6);
    int j = threadIdx.x & 63;
    if (node >= N) return;
    float a0 = aggx[node * 3], a1 = aggx[node * 3 + 1], a2 = aggx[node * 3 + 2];
    float acc = bp[j];
    acc = fmaf(a0, Wp[j], acc);
    acc = fmaf(a1, Wp[64 + j], acc);
    acc = fmaf(a2, Wp[128 + j], acc);
    t[(size_t)node * 64 + j] = fmaxf(acc, 0.f);
}

// main matmul: C[N,64] = A[N,64] @ W[64,64]; optional recall epilogue
//   + aggx[N,3] @ Wx[3,64] + br[64]
// tile: 96 rows x 64 cols per block, 96 threads, 8 rows x 4 f32x2-pairs per thread
__global__ void k_mm96(const float* __restrict__ A, const float* __restrict__ W,
                       const float* __restrict__ Wx, const float* __restrict__ brv,
                       const float* __restrict__ aggx, float* __restrict__ C, int N) {
    __shared__ float As[96][65];
    __shared__ float Ws[64][64];
    int tid = threadIdx.x;
    int row0 = blockIdx.x * 96;
    {
        const float4* Wv = (const float4*)W;
        float4* Wsv = (float4*)Ws;
        for (int i = tid; i < 1024; i += 96) Wsv[i] = Wv[i];
    }
    for (int i = tid; i < 96 * 16; i += 96) {
        int r = i >> 4, kq = i & 15;
        int row = row0 + r;
        float4 v = make_float4(0.f, 0.f, 0.f, 0.f);
        if (row < N) v = ((const float4*)A)[(size_t)row * 16 + kq];
        As[r][kq * 4 + 0] = v.x;
        As[r][kq * 4 + 1] = v.y;
        As[r][kq * 4 + 2] = v.z;
        As[r][kq * 4 + 3] = v.w;
    }
    __syncthreads();

    int tx = tid & 7, ty = tid >> 3;   // tx: col octet, ty: row octet (0..11)
    u64 acc2[8][4];
#pragma unroll
    for (int i = 0; i < 8; i++)
#pragma unroll
        for (int j = 0; j < 4; j++) acc2[i][j] = 0ull;

#pragma unroll 8
    for (int k = 0; k < 64; k++) {
        u64 ad[8];
#pragma unroll
        for (int i = 0; i < 8; i++) {
            float a = As[ty * 8 + i][k];
            ad[i] = pack2(a, a);
        }
        // 4 packed W pairs (Ws row is 16B-aligned at tx*8 floats)
        const u64* wp = (const u64*)&Ws[k][tx * 8];
        u64 w0 = wp[0], w1 = wp[1], w2 = wp[2], w3 = wp[3];
#pragma unroll
        for (int i = 0; i < 8; i++) {
            ffma2(acc2[i][0], ad[i], w0);
            ffma2(acc2[i][1], ad[i], w1);
            ffma2(acc2[i][2], ad[i], w2);
            ffma2(acc2[i][3], ad[i], w3);
        }
    }

    bool recall = (aggx != nullptr);
    float wxr[3][8], brr[8];
    if (recall) {
#pragma unroll
        for (int j = 0; j < 8; j++) {
            int col = tx * 8 + j;
            wxr[0][j] = Wx[col];
            wxr[1][j] = Wx[64 + col];
            wxr[2][j] = Wx[128 + col];
            brr[j] = brv[col];
        }
    }
#pragma unroll
    for (int i = 0; i < 8; i++) {
        int row = row0 + ty * 8 + i;
        if (row >= N) continue;
        float acc[8];
#pragma unroll
        for (int j = 0; j < 4; j++) unpack2(acc2[i][j], acc[2 * j], acc[2 * j + 1]);
        if (recall) {
            float a0 = aggx[row * 3], a1 = aggx[row * 3 + 1], a2 = aggx[row * 3 + 2];
#pragma unroll
            for (int j = 0; j < 8; j++) {
                acc[j] += fmaf(a0, wxr[0][j],
                           fmaf(a1, wxr[1][j], fmaf(a2, wxr[2][j], brr[j])));
            }
        }
        float4 o0 = make_float4(acc[0], acc[1], acc[2], acc[3]);
        float4 o1 = make_float4(acc[4], acc[5], acc[6], acc[7]);
        ((float4*)C)[(size_t)row * 16 + tx * 2 + 0] = o0;
        ((float4*)C)[(size_t)row * 16 + tx * 2 + 1] = o1;
    }
}

// small head matmuls: warp per node
template <int FIN, int FOUT>
__global__ void k_mm_small(const float* __restrict__ A, const float* __restrict__ W,
                           float* __restrict__ C, int N) {
    __shared__ float Ws[FIN * FOUT + 32];
    int tid = threadIdx.x;
    for (int i = tid; i < FIN * FOUT; i += blockDim.x) Ws[i] = W[i];
    for (int i = FIN * FOUT + tid; i < FIN * FOUT + 32; i += blockDim.x) Ws[i] = 0.f;
    __syncthreads();
    int node = blockIdx.x * 4 + (tid >> 5);
    int j = tid & 31;
    if (node >= N) return;
    float acc = 0.f;
    const float* a = A + (size_t)node * FIN;
#pragma unroll
    for (int k = 0; k < FIN; k++) {
        float av = __ldg(a + k);
        acc = fmaf(av, Ws[k * FOUT + j], acc);
    }
    if (j < FOUT) C[(size_t)node * FOUT + j] = acc;
}

// =============== host launch ===============

extern "C" void kernel_launch(void* const* d_in, const int* in_sizes, int n_in,
                              void* d_out, int out_size) {
    const float* x   = (const float*)d_in[0];
    const float* Wp  = (const float*)d_in[1];
    const float* bp  = (const float*)d_in[2];
    const float* Wr  = (const float*)d_in[3];
    const float* br  = (const float*)d_in[4];
    const float* W11 = (const float*)d_in[5];
    const float* b11 = (const float*)d_in[6];
    const float* W12 = (const float*)d_in[7];
    const float* b12 = (const float*)d_in[8];
    const float* W21 = (const float*)d_in[9];
    const float* b21 = (const float*)d_in[10];
    const float* W22 = (const float*)d_in[11];
    const float* b22 = (const float*)d_in[12];
    const float* Wh1 = (const float*)d_in[13];
    const float* bh1 = (const float*)d_in[14];
    const float* Wh2 = (const float*)d_in[15];
    const float* bh2 = (const float*)d_in[16];
    const float* Wh3 = (const float*)d_in[17];
    const float* bh3 = (const float*)d_in[18];
    const int*   ei  = (const int*)d_in[19];

    int N = in_sizes[0] / 3;
    int E = in_sizes[19] / 2;
    const int* esrc = ei;
    const int* edst = ei + E;

    int *counts, *rowoff, *bsums;
    float *dis, *aggx;
    EdgeRec* edges;
    float4 *t4, *u4, *v4;
    cudaGetSymbolAddress((void**)&counts, g_counts);
    cudaGetSymbolAddress((void**)&rowoff, g_rowoff);
    cudaGetSymbolAddress((void**)&bsums, g_bsums);
    cudaGetSymbolAddress((void**)&dis, g_dis);
    cudaGetSymbolAddress((void**)&edges, g_edges);
    cudaGetSymbolAddress((void**)&aggx, g_aggx);
    cudaGetSymbolAddress((void**)&t4, g_t);
    cudaGetSymbolAddress((void**)&u4, g_u);
    cudaGetSymbolAddress((void**)&v4, g_v);
    float* t = (float*)t4;
    float* u = (float*)u4;
    float* v = (float*)v4;

    int nbE = (E + 255) / 256;
    int nbN = (N + 255) / 256;
    int nbScan = (N + 511) / 512;
    int nbWarp = (N + 7) / 8;       // 8 nodes per 256-thread block
    int nbMM = (N + 95) / 96;
    int nbW4 = (N + 3) / 4;         // 4 nodes per 128/256-thread block

    // ---- graph setup ----
    cudaMemsetAsync(counts, 0, (size_t)N * sizeof(int), 0);
    k_count<<<nbE, 256>>>(edst, E, counts);
    k_dis<<<nbN, 256>>>(counts, dis, N);
    k_scan1<<<nbScan, 512>>>(counts, rowoff, bsums, N);
    k_scan2<<<1, 256>>>(bsums, nbScan);
    k_scan3<<<nbScan, 512>>>(rowoff, bsums, N, E);
    cudaMemsetAsync(counts, 0, (size_t)N * sizeof(int), 0);
    k_fill<<<nbE, 256>>>(esrc, edst, E, rowoff, counts, dis, edges);

    // ---- loop-invariant: agg(x) and projection ----
    k_agg_t<3><<<nbN, 256>>>(x, edges, rowoff, dis, nullptr, 0, aggx, N);
    k_proj<<<nbW4, 256>>>(aggx, Wp, bp, t, N);

    const float* Wrx = Wr + 64 * 64;  // rows 64..66 of Wr (x part)

    // ---- iterations ----
    for (int it = 0; it < ITERS; it++) {
        // recall: t = agg(t) @ Wr_t + aggx @ Wr_x + br
        k_agg64<<<nbWarp, 256>>>(t, edges, rowoff, dis, nullptr, nullptr, 0, v, N);
        k_mm96<<<nbMM, 96>>>(v, Wr, Wrx, br, aggx, t, N);
        // block 1
        k_mm96<<<nbMM, 96>>>(t, W11, nullptr, nullptr, nullptr, u, N);
        k_agg64<<<nbWarp, 256>>>(u, edges, rowoff, dis, b11, nullptr, 1, v, N);
        k_mm96<<<nbMM, 96>>>(v, W12, nullptr, nullptr, nullptr, u, N);
        k_agg64<<<nbWarp, 256>>>(u, edges, rowoff, dis, b12, t, 1, t, N);
        // block 2
        k_mm96<<<nbMM, 96>>>(t, W21, nullptr, nullptr, nullptr, u, N);
        k_agg64<<<nbWarp, 256>>>(u, edges, rowoff, dis, b21, nullptr, 1, v, N);
        k_mm96<<<nbMM, 96>>>(v, W22, nullptr, nullptr, nullptr, u, N);
        k_agg64<<<nbWarp, 256>>>(u, edges, rowoff, dis, b22, t, 1, t, N);
    }

    // ---- head ----
    k_mm_small<64, 32><<<nbW4, 128>>>(t, Wh1, u, N);
    k_agg32<<<nbWarp, 256>>>(u, edges, rowoff, dis, bh1, 1, v, N);
    k_mm_small<32, 8><<<nbW4, 128>>>(v, Wh2, u, N);
    k_agg_t<8><<<nbN, 256>>>(u, edges, rowoff, dis, bh2, 1, v, N);
    k_mm_small<8, 2><<<nbW4, 128>>>(v, Wh3, u, N);
    k_agg_t<2><<<nbN, 256>>>(u, edges, rowoff, dis, bh3, 0, (float*)d_out, N);
}

// round 6
// speedup vs baseline: 2.3148x; 1.0075x over previous
#include <cuda_runtime.h>
#include <math.h>

// Problem-fixed capacities (dataset constants)
#define NCAP 100000
#define ECAP 1600000
#define ITERS 5

struct __align__(8) EdgeRec { int src; float w; };
typedef unsigned long long u64;

// ---- static device scratch (no allocation allowed) ----
__device__ int     g_counts[NCAP];
__device__ int     g_rowoff[NCAP + 1];
__device__ int     g_bsums[1024];
__device__ float   g_dis[NCAP];
__device__ EdgeRec g_edges[ECAP];
__device__ float   g_aggx[NCAP * 3];
// float4-typed to guarantee 16B alignment for vector loads
__device__ float4  g_t[NCAP * 16];
__device__ float4  g_u[NCAP * 16];
__device__ float4  g_v[NCAP * 16];

// ---- packed fp32x2 helpers (Blackwell FFMA2 path) ----
__device__ __forceinline__ u64 pack2(float x, float y) {
    u64 r; asm("mov.b64 %0, {%1, %2};" : "=l"(r) : "f"(x), "f"(y)); return r;
}
__device__ __forceinline__ void unpack2(u64 v, float& x, float& y) {
    asm("mov.b64 {%0, %1}, %2;" : "=f"(x), "=f"(y) : "l"(v));
}
__device__ __forceinline__ void ffma2(u64& d, u64 a, u64 b) {
    asm("fma.rn.f32x2 %0, %1, %2, %0;" : "+l"(d) : "l"(a), "l"(b));
}

// =============== graph setup kernels ===============

__global__ void k_count(const int* __restrict__ dst, int E, int* __restrict__ counts) {
    int i = blockIdx.x * blockDim.x + threadIdx.x;
    if (i < E) atomicAdd(&counts[dst[i]], 1);
}

__global__ void k_dis(const int* __restrict__ counts, float* __restrict__ dis, int N) {
    int i = blockIdx.x * blockDim.x + threadIdx.x;
    if (i < N) dis[i] = rsqrtf((float)(counts[i] + 1));   // +1 self loop
}

// exclusive scan of counts -> rowoff, 3-phase
__global__ void k_scan1(const int* __restrict__ counts, int* __restrict__ out,
                        int* __restrict__ bsums, int n) {
    __shared__ int s[512];
    int tid = threadIdx.x;
    int i = blockIdx.x * 512 + tid;
    int v = (i < n) ? counts[i] : 0;
    s[tid] = v;
    __syncthreads();
    for (int off = 1; off < 512; off <<= 1) {
        int t = 0;
        if (tid >= off) t = s[tid - off];
        __syncthreads();
        s[tid] += t;
        __syncthreads();
    }
    if (i < n) out[i] = s[tid] - v;           // exclusive
    if (tid == 511) bsums[blockIdx.x] = s[511];
}

__global__ void k_scan2(int* __restrict__ bsums, int nb) {
    __shared__ int s[256];
    int tid = threadIdx.x;
    int v = (tid < nb) ? bsums[tid] : 0;
    s[tid] = v;
    __syncthreads();
    for (int off = 1; off < 256; off <<= 1) {
        int t = 0;
        if (tid >= off) t = s[tid - off];
        __syncthreads();
        s[tid] += t;
        __syncthreads();
    }
    if (tid < nb) bsums[tid] = s[tid] - v;
}

__global__ void k_scan3(int* __restrict__ out, const int* __restrict__ bsums, int n, int E) {
    int i = blockIdx.x * 512 + threadIdx.x;
    if (i < n) out[i] += bsums[blockIdx.x];
    if (i == 0) out[n] = E;
}

__global__ void k_fill(const int* __restrict__ srcA, const int* __restrict__ dstA, int E,
                       const int* __restrict__ rowoff, int* __restrict__ cursor,
                       const float* __restrict__ dis, EdgeRec* __restrict__ edges) {
    int i = blockIdx.x * blockDim.x + threadIdx.x;
    if (i >= E) return;
    int s = srcA[i], d = dstA[i];
    int pos = rowoff[d] + atomicAdd(&cursor[d], 1);
    EdgeRec r;
    r.src = s;
    r.w = dis[s] * dis[d];
    edges[pos] = r;
}

// =============== fused GCN layer (warp-scope agg -> mm) ===============
// out[N,64] = epi( agg(Hin)[N,64] @ W[64,64] + bias )
// epi: (+ aggx@Wx if RECALL) (+ res if RES) (relu if RELU)
// Each warp: gather 4 nodes (reg accumulators) -> private smem As[64][4]
// -> 4x64 @ 64x64 matmul with W in block smem, FFMA2 accumulators.
template <int RECALL, int RES, int RELU>
__global__ void __launch_bounds__(256) k_layer(
    const float* __restrict__ Hin, const EdgeRec* __restrict__ edges,
    const int* __restrict__ rowoff, const float* __restrict__ dis,
    const float* __restrict__ W, const float* __restrict__ bias,
    const float* __restrict__ res,
    const float* __restrict__ aggx, const float* __restrict__ Wx,
    float* __restrict__ out, int N) {
    __shared__ float Ws[64][64];       // 16 KB
    __shared__ float As[8][64][4];     // 8 KB (1 KB per warp)
    int tid = threadIdx.x;
    int lane = tid & 31, warp = tid >> 5;
    {
        const float4* Wv = (const float4*)W;
        float4* Wsv = (float4*)&Ws[0][0];
        for (int i = tid; i < 1024; i += 256) Wsv[i] = Wv[i];
    }
    __syncthreads();

    int node0 = (blockIdx.x * 8 + warp) * 4;
    const float2* U = (const float2*)Hin;
    float (*Aw)[4] = As[warp];

    // ---- gather phase: 4 nodes per warp ----
#pragma unroll
    for (int n = 0; n < 4; n++) {
        int node = node0 + n;
        float2 a0 = make_float2(0.f, 0.f), a1 = a0, a2 = a0, a3 = a0;
        if (node < N) {
            int e0 = rowoff[node], e1 = rowoff[node + 1];
            int e = e0;
            for (; e + 4 <= e1; e += 4) {
                EdgeRec r0 = edges[e],     r1 = edges[e + 1];
                EdgeRec r2 = edges[e + 2], r3 = edges[e + 3];
                float2 f0 = U[(size_t)r0.src * 32 + lane];
                float2 f1 = U[(size_t)r1.src * 32 + lane];
                float2 f2 = U[(size_t)r2.src * 32 + lane];
                float2 f3 = U[(size_t)r3.src * 32 + lane];
                a0.x = fmaf(r0.w, f0.x, a0.x); a0.y = fmaf(r0.w, f0.y, a0.y);
                a1.x = fmaf(r1.w, f1.x, a1.x); a1.y = fmaf(r1.w, f1.y, a1.y);
                a2.x = fmaf(r2.w, f2.x, a2.x); a2.y = fmaf(r2.w, f2.y, a2.y);
                a3.x = fmaf(r3.w, f3.x, a3.x); a3.y = fmaf(r3.w, f3.y, a3.y);
            }
            for (; e < e1; e++) {
                EdgeRec rr = edges[e];
                float2 f = U[(size_t)rr.src * 32 + lane];
                a0.x = fmaf(rr.w, f.x, a0.x); a0.y = fmaf(rr.w, f.y, a0.y);
            }
            float dv = dis[node];
            float sw = dv * dv;
            float2 fs = U[(size_t)node * 32 + lane];
            a1.x = fmaf(sw, fs.x, a1.x); a1.y = fmaf(sw, fs.y, a1.y);
        }
        Aw[2 * lane][n]     = (a0.x + a1.x) + (a2.x + a3.x);
        Aw[2 * lane + 1][n] = (a0.y + a1.y) + (a2.y + a3.y);
    }
    __syncwarp();

    // ---- mm phase: lane handles cols (2*lane, 2*lane+1) for 4 nodes ----
    u64 o0 = 0ull, o1 = 0ull, o2 = 0ull, o3 = 0ull;
#pragma unroll 8
    for (int k = 0; k < 64; k++) {
        float4 av = *(const float4*)&Aw[k][0];        // broadcast (16B aligned)
        u64 wp = *(const u64*)&Ws[k][2 * lane];       // conflict-free 8B
        ffma2(o0, pack2(av.x, av.x), wp);
        ffma2(o1, pack2(av.y, av.y), wp);
        ffma2(o2, pack2(av.z, av.z), wp);
        ffma2(o3, pack2(av.w, av.w), wp);
    }

    // ---- epilogue ----
    float2 b2 = ((const float2*)bias)[lane];
    float2 wx0, wx1, wx2;
    if (RECALL) {
        wx0 = ((const float2*)Wx)[lane];
        wx1 = ((const float2*)Wx)[32 + lane];
        wx2 = ((const float2*)Wx)[64 + lane];
    }
    u64 oo[4] = {o0, o1, o2, o3};
#pragma unroll
    for (int n = 0; n < 4; n++) {
        int node = node0 + n;
        if (node >= N) continue;
        float cx, cy;
        unpack2(oo[n], cx, cy);
        cx += b2.x; cy += b2.y;
        if (RECALL) {
            float g0 = aggx[node * 3], g1 = aggx[node * 3 + 1], g2 = aggx[node * 3 + 2];
            cx = fmaf(g0, wx0.x, fmaf(g1, wx1.x, fmaf(g2, wx2.x, cx)));
            cy = fmaf(g0, wx0.y, fmaf(g1, wx1.y, fmaf(g2, wx2.y, cy)));
        }
        if (RES) {
            float2 rr = ((const float2*)res)[(size_t)node * 32 + lane];
            cx += rr.x; cy += rr.y;
        }
        if (RELU) {
            cx = fmaxf(cx, 0.f);
            cy = fmaxf(cy, 0.f);
        }
        ((float2*)out)[(size_t)node * 32 + lane] = make_float2(cx, cy);
    }
}

// =============== head aggregation kernels ===============

// width-32: warp per node
__global__ void k_agg32(const float* __restrict__ u, const EdgeRec* __restrict__ edges,
                        const int* __restrict__ rowoff, const float* __restrict__ dis,
                        const float* __restrict__ bias, int relu,
                        float* __restrict__ out, int N) {
    int node = blockIdx.x * 8 + (threadIdx.x >> 5);
    int lane = threadIdx.x & 31;
    if (node >= N) return;
    float acc = 0.f;
    int e0 = rowoff[node], e1 = rowoff[node + 1];
    for (int e = e0; e < e1; e++) {
        EdgeRec r = edges[e];
        acc = fmaf(r.w, u[(size_t)r.src * 32 + lane], acc);
    }
    float dv = dis[node];
    acc = fmaf(dv * dv, u[(size_t)node * 32 + lane], acc);
    if (bias) acc += bias[lane];
    if (relu) acc = fmaxf(acc, 0.f);
    out[(size_t)node * 32 + lane] = acc;
}

// small widths (2,3,8): thread per node
template <int W>
__global__ void k_agg_t(const float* __restrict__ u, const EdgeRec* __restrict__ edges,
                        const int* __restrict__ rowoff, const float* __restrict__ dis,
                        const float* __restrict__ bias, int relu,
                        float* __restrict__ out, int N) {
    int node = blockIdx.x * blockDim.x + threadIdx.x;
    if (node >= N) return;
    float acc[W];
#pragma unroll
    for (int k = 0; k < W; k++) acc[k] = 0.f;
    int e0 = rowoff[node], e1 = rowoff[node + 1];
    for (int e = e0; e < e1; e++) {
        EdgeRec r = edges[e];
        const float* up = u + (size_t)r.src * W;
#pragma unroll
        for (int k = 0; k < W; k++) acc[k] = fmaf(r.w, __ldg(up + k), acc[k]);
    }
    float dv = dis[node];
    float sw = dv * dv;
    const float* us = u + (size_t)node * W;
#pragma unroll
    for (int k = 0; k < W; k++) acc[k] = fmaf(sw, us[k], acc[k]);
    if (bias) {
#pragma unroll
        for (int k = 0; k < W; k++) acc[k] += bias[k];
    }
    if (relu) {
#pragma unroll
        for (int k = 0; k < W; k++) acc[k] = fmaxf(acc[k], 0.f);
    }
#pragma unroll
    for (int k = 0; k < W; k++) out[(size_t)node * W + k] = acc[k];
}

// =============== small dense kernels ===============

// projection: t = relu(aggx @ Wp + bp), Wp [3,64]
__global__ void k_proj(const float* __restrict__ aggx, const float* __restrict__ Wp,
                       const float* __restrict__ bp, float* __restrict__ t, int N) {
    int node = blockIdx.x * 4 + (threadIdx.x >> 6);
    int j = threadIdx.x & 63;
    if (node >= N) return;
    float a0 = aggx[node * 3], a1 = aggx[node * 3 + 1], a2 = aggx[node * 3 + 2];
    float acc = bp[j];
    acc = fmaf(a0, Wp[j], acc);
    acc = fmaf(a1, Wp[64 + j], acc);
    acc = fmaf(a2, Wp[128 + j], acc);
    t[(size_t)node * 64 + j] = fmaxf(acc, 0.f);
}

// small head matmuls: warp per node
template <int FIN, int FOUT>
__global__ void k_mm_small(const float* __restrict__ A, const float* __restrict__ W,
                           float* __restrict__ C, int N) {
    __shared__ float Ws[FIN * FOUT + 32];
    int tid = threadIdx.x;
    for (int i = tid; i < FIN * FOUT; i += blockDim.x) Ws[i] = W[i];
    for (int i = FIN * FOUT + tid; i < FIN * FOUT + 32; i += blockDim.x) Ws[i] = 0.f;
    __syncthreads();
    int node = blockIdx.x * 4 + (tid >> 5);
    int j = tid & 31;
    if (node >= N) return;
    float acc = 0.f;
    const float* a = A + (size_t)node * FIN;
#pragma unroll
    for (int k = 0; k < FIN; k++) {
        float av = __ldg(a + k);
        acc = fmaf(av, Ws[k * FOUT + j], acc);
    }
    if (j < FOUT) C[(size_t)node * FOUT + j] = acc;
}

// =============== host launch ===============

extern "C" void kernel_launch(void* const* d_in, const int* in_sizes, int n_in,
                              void* d_out, int out_size) {
    const float* x   = (const float*)d_in[0];
    const float* Wp  = (const float*)d_in[1];
    const float* bp  = (const float*)d_in[2];
    const float* Wr  = (const float*)d_in[3];
    const float* br  = (const float*)d_in[4];
    const float* W11 = (const float*)d_in[5];
    const float* b11 = (const float*)d_in[6];
    const float* W12 = (const float*)d_in[7];
    const float* b12 = (const float*)d_in[8];
    const float* W21 = (const float*)d_in[9];
    const float* b21 = (const float*)d_in[10];
    const float* W22 = (const float*)d_in[11];
    const float* b22 = (const float*)d_in[12];
    const float* Wh1 = (const float*)d_in[13];
    const float* bh1 = (const float*)d_in[14];
    const float* Wh2 = (const float*)d_in[15];
    const float* bh2 = (const float*)d_in[16];
    const float* Wh3 = (const float*)d_in[17];
    const float* bh3 = (const float*)d_in[18];
    const int*   ei  = (const int*)d_in[19];

    int N = in_sizes[0] / 3;
    int E = in_sizes[19] / 2;
    const int* esrc = ei;
    const int* edst = ei + E;

    int *counts, *rowoff, *bsums;
    float *dis, *aggx;
    EdgeRec* edges;
    float4 *t4, *u4, *v4;
    cudaGetSymbolAddress((void**)&counts, g_counts);
    cudaGetSymbolAddress((void**)&rowoff, g_rowoff);
    cudaGetSymbolAddress((void**)&bsums, g_bsums);
    cudaGetSymbolAddress((void**)&dis, g_dis);
    cudaGetSymbolAddress((void**)&edges, g_edges);
    cudaGetSymbolAddress((void**)&aggx, g_aggx);
    cudaGetSymbolAddress((void**)&t4, g_t);
    cudaGetSymbolAddress((void**)&u4, g_u);
    cudaGetSymbolAddress((void**)&v4, g_v);
    float* bufs[3] = {(float*)t4, (float*)u4, (float*)v4};

    int nbE = (E + 255) / 256;
    int nbN = (N + 255) / 256;
    int nbScan = (N + 511) / 512;
    int nbWarp = (N + 7) / 8;       // 8 nodes per 256-thread block
    int nbL = (N + 31) / 32;        // fused layer: 32 nodes per 256-thread block
    int nbW4 = (N + 3) / 4;

    // ---- graph setup ----
    cudaMemsetAsync(counts, 0, (size_t)N * sizeof(int), 0);
    k_count<<<nbE, 256>>>(edst, E, counts);
    k_dis<<<nbN, 256>>>(counts, dis, N);
    k_scan1<<<nbScan, 512>>>(counts, rowoff, bsums, N);
    k_scan2<<<1, 256>>>(bsums, nbScan);
    k_scan3<<<nbScan, 512>>>(rowoff, bsums, N, E);
    cudaMemsetAsync(counts, 0, (size_t)N * sizeof(int), 0);
    k_fill<<<nbE, 256>>>(esrc, edst, E, rowoff, counts, dis, edges);

    // ---- loop-invariant: agg(x) and projection ----
    k_agg_t<3><<<nbN, 256>>>(x, edges, rowoff, dis, nullptr, 0, aggx, N);
    k_proj<<<nbW4, 256>>>(aggx, Wp, bp, bufs[0], N);

    const float* Wrx = Wr + 64 * 64;  // rows 64..66 of Wr (x part)

    // ---- iterations: 5 fused GCN layers per iteration ----
    int si = 0;  // state buffer index
    for (int it = 0; it < ITERS; it++) {
        float* S = bufs[si];
        float* A = bufs[(si + 1) % 3];
        float* B = bufs[(si + 2) % 3];
        // recall: A = agg(S)@Wr_t + aggx@Wr_x + br
        k_layer<1, 0, 0><<<nbL, 256>>>(S, edges, rowoff, dis, Wr, br,
                                       nullptr, aggx, Wrx, A, N);
        // block 1: B = relu(agg(A)@W11 + b11); S = relu(agg(B)@W12 + b12 + A)
        k_layer<0, 0, 1><<<nbL, 256>>>(A, edges, rowoff, dis, W11, b11,
                                       nullptr, nullptr, nullptr, B, N);
        k_layer<0, 1, 1><<<nbL, 256>>>(B, edges, rowoff, dis, W12, b12,
                                       A, nullptr, nullptr, S, N);
        // block 2: A = relu(agg(S)@W21 + b21); B = relu(agg(A)@W22 + b22 + S)
        k_layer<0, 0, 1><<<nbL, 256>>>(S, edges, rowoff, dis, W21, b21,
                                       nullptr, nullptr, nullptr, A, N);
        k_layer<0, 1, 1><<<nbL, 256>>>(A, edges, rowoff, dis, W22, b22,
                                       S, nullptr, nullptr, B, N);
        si = (si + 2) % 3;   // state is now B
    }

    float* S  = bufs[si];
    float* h1 = bufs[(si + 1) % 3];
    float* h2 = bufs[(si + 2) % 3];

    // ---- head ----
    k_mm_small<64, 32><<<nbW4, 128>>>(S, Wh1, h1, N);
    k_agg32<<<nbWarp, 256>>>(h1, edges, rowoff, dis, bh1, 1, h2, N);
    k_mm_small<32, 8><<<nbW4, 128>>>(h2, Wh2, h1, N);
    k_agg_t<8><<<nbN, 256>>>(h1, edges, rowoff, dis, bh2, 1, h2, N);
    k_mm_small<8, 2><<<nbW4, 128>>>(h2, Wh3, h1, N);
    k_agg_t<2><<<nbN, 256>>>(h1, edges, rowoff, dis, bh3, 0, (float*)d_out, N);
}

// round 7
// speedup vs baseline: 2.3480x; 1.0143x over previous
#include <cuda_runtime.h>
#include <cuda_fp16.h>
#include <math.h>

// Problem-fixed capacities (dataset constants)
#define NCAP 100000
#define ECAP 1600000
#define ITERS 5

struct __align__(8) EdgeRec { int src; float w; };
typedef unsigned long long u64;
typedef unsigned int u32;

// ---- static device scratch (no allocation allowed) ----
__device__ int     g_counts[NCAP];
__device__ int     g_rowoff[NCAP + 1];
__device__ int     g_bsums[1024];
__device__ float   g_dis[NCAP];
__device__ EdgeRec g_edges[ECAP];
__device__ float   g_aggx[NCAP * 3];
// float4-typed to guarantee 16B alignment for vector loads
__device__ float4  g_t[NCAP * 16];
__device__ float4  g_u[NCAP * 16];
__device__ float4  g_v[NCAP * 16];
// fp16 mirrors (32 half2 = 8 uint4 per node)
__device__ uint4   g_t16[NCAP * 8];
__device__ uint4   g_u16[NCAP * 8];

// ---- packed fp32x2 helpers (Blackwell FFMA2 path) ----
__device__ __forceinline__ u64 pack2(float x, float y) {
    u64 r; asm("mov.b64 %0, {%1, %2};" : "=l"(r) : "f"(x), "f"(y)); return r;
}
__device__ __forceinline__ void unpack2(u64 v, float& x, float& y) {
    asm("mov.b64 {%0, %1}, %2;" : "=f"(x), "=f"(y) : "l"(v));
}
__device__ __forceinline__ void ffma2(u64& d, u64 a, u64 b) {
    asm("fma.rn.f32x2 %0, %1, %2, %0;" : "+l"(d) : "l"(a), "l"(b));
}

// ---- fp16 pack/unpack ----
__device__ __forceinline__ float2 h2f(u32 q) {
    __half2 h = *reinterpret_cast<__half2*>(&q);
    return __half22float2(h);
}
__device__ __forceinline__ u32 f2h(float x, float y) {
    __half2 h = __floats2half2_rn(x, y);
    return *reinterpret_cast<u32*>(&h);
}

// =============== graph setup kernels ===============

__global__ void k_count(const int* __restrict__ dst, int E, int* __restrict__ counts) {
    int i = blockIdx.x * blockDim.x + threadIdx.x;
    if (i < E) atomicAdd(&counts[dst[i]], 1);
}

__global__ void k_dis(const int* __restrict__ counts, float* __restrict__ dis, int N) {
    int i = blockIdx.x * blockDim.x + threadIdx.x;
    if (i < N) dis[i] = rsqrtf((float)(counts[i] + 1));   // +1 self loop
}

// exclusive scan of counts -> rowoff, 3-phase
__global__ void k_scan1(const int* __restrict__ counts, int* __restrict__ out,
                        int* __restrict__ bsums, int n) {
    __shared__ int s[512];
    int tid = threadIdx.x;
    int i = blockIdx.x * 512 + tid;
    int v = (i < n) ? counts[i] : 0;
    s[tid] = v;
    __syncthreads();
    for (int off = 1; off < 512; off <<= 1) {
        int t = 0;
        if (tid >= off) t = s[tid - off];
        __syncthreads();
        s[tid] += t;
        __syncthreads();
    }
    if (i < n) out[i] = s[tid] - v;           // exclusive
    if (tid == 511) bsums[blockIdx.x] = s[511];
}

__global__ void k_scan2(int* __restrict__ bsums, int nb) {
    __shared__ int s[256];
    int tid = threadIdx.x;
    int v = (tid < nb) ? bsums[tid] : 0;
    s[tid] = v;
    __syncthreads();
    for (int off = 1; off < 256; off <<= 1) {
        int t = 0;
        if (tid >= off) t = s[tid - off];
        __syncthreads();
        s[tid] += t;
        __syncthreads();
    }
    if (tid < nb) bsums[tid] = s[tid] - v;
}

__global__ void k_scan3(int* __restrict__ out, const int* __restrict__ bsums, int n, int E) {
    int i = blockIdx.x * 512 + threadIdx.x;
    if (i < n) out[i] += bsums[blockIdx.x];
    if (i == 0) out[n] = E;
}

__global__ void k_fill(const int* __restrict__ srcA, const int* __restrict__ dstA, int E,
                       const int* __restrict__ rowoff, int* __restrict__ cursor,
                       const float* __restrict__ dis, EdgeRec* __restrict__ edges) {
    int i = blockIdx.x * blockDim.x + threadIdx.x;
    if (i >= E) return;
    int s = srcA[i], d = dstA[i];
    int pos = rowoff[d] + atomicAdd(&cursor[d], 1);
    EdgeRec r;
    r.src = s;
    r.w = dis[s] * dis[d];
    edges[pos] = r;
}

// =============== aggregation kernels ===============

// width-64 fp16-gather: warp per node, half2 per lane, fp32 accumulation
template <int RELU, int RES, int MIRROR>
__global__ void k_agg64h(const u32* __restrict__ U16, const EdgeRec* __restrict__ edges,
                         const int* __restrict__ rowoff, const float* __restrict__ dis,
                         const float* __restrict__ bias, const float* __restrict__ res,
                         float* __restrict__ out, u32* __restrict__ out16, int N) {
    int node = blockIdx.x * 8 + (threadIdx.x >> 5);
    int lane = threadIdx.x & 31;
    if (node >= N) return;
    float2 a0 = make_float2(0.f, 0.f), a1 = a0, a2 = a0, a3 = a0;
    int e0 = rowoff[node], e1 = rowoff[node + 1];
    int e = e0;
    for (; e + 4 <= e1; e += 4) {
        EdgeRec r0 = edges[e],     r1 = edges[e + 1];
        EdgeRec r2 = edges[e + 2], r3 = edges[e + 3];
        float2 f0 = h2f(U16[(size_t)r0.src * 32 + lane]);
        float2 f1 = h2f(U16[(size_t)r1.src * 32 + lane]);
        float2 f2 = h2f(U16[(size_t)r2.src * 32 + lane]);
        float2 f3 = h2f(U16[(size_t)r3.src * 32 + lane]);
        a0.x = fmaf(r0.w, f0.x, a0.x); a0.y = fmaf(r0.w, f0.y, a0.y);
        a1.x = fmaf(r1.w, f1.x, a1.x); a1.y = fmaf(r1.w, f1.y, a1.y);
        a2.x = fmaf(r2.w, f2.x, a2.x); a2.y = fmaf(r2.w, f2.y, a2.y);
        a3.x = fmaf(r3.w, f3.x, a3.x); a3.y = fmaf(r3.w, f3.y, a3.y);
    }
    for (; e < e1; e++) {
        EdgeRec rr = edges[e];
        float2 f = h2f(U16[(size_t)rr.src * 32 + lane]);
        a0.x = fmaf(rr.w, f.x, a0.x); a0.y = fmaf(rr.w, f.y, a0.y);
    }
    float dv = dis[node];
    float sw = dv * dv;
    float2 fs = h2f(U16[(size_t)node * 32 + lane]);
    a1.x = fmaf(sw, fs.x, a1.x); a1.y = fmaf(sw, fs.y, a1.y);
    float2 acc;
    acc.x = (a0.x + a1.x) + (a2.x + a3.x);
    acc.y = (a0.y + a1.y) + (a2.y + a3.y);
    if (bias) {
        float2 b = ((const float2*)bias)[lane];
        acc.x += b.x; acc.y += b.y;
    }
    if (RES) {
        float2 rr = ((const float2*)res)[(size_t)node * 32 + lane];
        acc.x += rr.x; acc.y += rr.y;
    }
    if (RELU) {
        acc.x = fmaxf(acc.x, 0.f);
        acc.y = fmaxf(acc.y, 0.f);
    }
    ((float2*)out)[(size_t)node * 32 + lane] = acc;
    if (MIRROR) out16[(size_t)node * 32 + lane] = f2h(acc.x, acc.y);
}

// width-32 fp32: warp per node (head)
__global__ void k_agg32(const float* __restrict__ u, const EdgeRec* __restrict__ edges,
                        const int* __restrict__ rowoff, const float* __restrict__ dis,
                        const float* __restrict__ bias, int relu,
                        float* __restrict__ out, int N) {
    int node = blockIdx.x * 8 + (threadIdx.x >> 5);
    int lane = threadIdx.x & 31;
    if (node >= N) return;
    float acc = 0.f;
    int e0 = rowoff[node], e1 = rowoff[node + 1];
    for (int e = e0; e < e1; e++) {
        EdgeRec r = edges[e];
        acc = fmaf(r.w, u[(size_t)r.src * 32 + lane], acc);
    }
    float dv = dis[node];
    acc = fmaf(dv * dv, u[(size_t)node * 32 + lane], acc);
    if (bias) acc += bias[lane];
    if (relu) acc = fmaxf(acc, 0.f);
    out[(size_t)node * 32 + lane] = acc;
}

// small widths (2,3,8): thread per node
template <int W>
__global__ void k_agg_t(const float* __restrict__ u, const EdgeRec* __restrict__ edges,
                        const int* __restrict__ rowoff, const float* __restrict__ dis,
                        const float* __restrict__ bias, int relu,
                        float* __restrict__ out, int N) {
    int node = blockIdx.x * blockDim.x + threadIdx.x;
    if (node >= N) return;
    float acc[W];
#pragma unroll
    for (int k = 0; k < W; k++) acc[k] = 0.f;
    int e0 = rowoff[node], e1 = rowoff[node + 1];
    for (int e = e0; e < e1; e++) {
        EdgeRec r = edges[e];
        const float* up = u + (size_t)r.src * W;
#pragma unroll
        for (int k = 0; k < W; k++) acc[k] = fmaf(r.w, __ldg(up + k), acc[k]);
    }
    float dv = dis[node];
    float sw = dv * dv;
    const float* us = u + (size_t)node * W;
#pragma unroll
    for (int k = 0; k < W; k++) acc[k] = fmaf(sw, us[k], acc[k]);
    if (bias) {
#pragma unroll
        for (int k = 0; k < W; k++) acc[k] += bias[k];
    }
    if (relu) {
#pragma unroll
        for (int k = 0; k < W; k++) acc[k] = fmaxf(acc[k], 0.f);
    }
#pragma unroll
    for (int k = 0; k < W; k++) out[(size_t)node * W + k] = acc[k];
}

// =============== dense kernels ===============

// projection: t = relu(aggx @ Wp + bp), fp32 + fp16 mirror
__global__ void k_proj(const float* __restrict__ aggx, const float* __restrict__ Wp,
                       const float* __restrict__ bp, float* __restrict__ t,
                       u32* __restrict__ t16, int N) {
    int node = blockIdx.x * 4 + (threadIdx.x >> 6);
    int j = threadIdx.x & 63;
    if (node >= N) return;
    float a0 = aggx[node * 3], a1 = aggx[node * 3 + 1], a2 = aggx[node * 3 + 2];
    float acc = bp[j];
    acc = fmaf(a0, Wp[j], acc);
    acc = fmaf(a1, Wp[64 + j], acc);
    acc = fmaf(a2, Wp[128 + j], acc);
    acc = fmaxf(acc, 0.f);
    t[(size_t)node * 64 + j] = acc;
    ((__half*)t16)[(size_t)node * 64 + j] = __float2half_rn(acc);
}

// shared mm body: accumulate 8x8 per thread with FFMA2
// recall variant (fp32 out + recall epilogue)
__global__ void k_mm96(const float* __restrict__ A, const float* __restrict__ W,
                       const float* __restrict__ Wx, const float* __restrict__ brv,
                       const float* __restrict__ aggx, float* __restrict__ C, int N) {
    __shared__ float As[96][65];
    __shared__ float Ws[64][64];
    int tid = threadIdx.x;
    int row0 = blockIdx.x * 96;
    {
        const float4* Wv = (const float4*)W;
        float4* Wsv = (float4*)Ws;
        for (int i = tid; i < 1024; i += 96) Wsv[i] = Wv[i];
    }
    for (int i = tid; i < 96 * 16; i += 96) {
        int r = i >> 4, kq = i & 15;
        int row = row0 + r;
        float4 v = make_float4(0.f, 0.f, 0.f, 0.f);
        if (row < N) v = ((const float4*)A)[(size_t)row * 16 + kq];
        As[r][kq * 4 + 0] = v.x;
        As[r][kq * 4 + 1] = v.y;
        As[r][kq * 4 + 2] = v.z;
        As[r][kq * 4 + 3] = v.w;
    }
    __syncthreads();

    int tx = tid & 7, ty = tid >> 3;
    u64 acc2[8][4];
#pragma unroll
    for (int i = 0; i < 8; i++)
#pragma unroll
        for (int j = 0; j < 4; j++) acc2[i][j] = 0ull;

#pragma unroll 8
    for (int k = 0; k < 64; k++) {
        u64 ad[8];
#pragma unroll
        for (int i = 0; i < 8; i++) {
            float a = As[ty * 8 + i][k];
            ad[i] = pack2(a, a);
        }
        const u64* wp = (const u64*)&Ws[k][tx * 8];
        u64 w0 = wp[0], w1 = wp[1], w2 = wp[2], w3 = wp[3];
#pragma unroll
        for (int i = 0; i < 8; i++) {
            ffma2(acc2[i][0], ad[i], w0);
            ffma2(acc2[i][1], ad[i], w1);
            ffma2(acc2[i][2], ad[i], w2);
            ffma2(acc2[i][3], ad[i], w3);
        }
    }

    float wxr[3][8], brr[8];
#pragma unroll
    for (int j = 0; j < 8; j++) {
        int col = tx * 8 + j;
        wxr[0][j] = Wx[col];
        wxr[1][j] = Wx[64 + col];
        wxr[2][j] = Wx[128 + col];
        brr[j] = brv[col];
    }
#pragma unroll
    for (int i = 0; i < 8; i++) {
        int row = row0 + ty * 8 + i;
        if (row >= N) continue;
        float acc[8];
#pragma unroll
        for (int j = 0; j < 4; j++) unpack2(acc2[i][j], acc[2 * j], acc[2 * j + 1]);
        float a0 = aggx[row * 3], a1 = aggx[row * 3 + 1], a2 = aggx[row * 3 + 2];
#pragma unroll
        for (int j = 0; j < 8; j++) {
            acc[j] += fmaf(a0, wxr[0][j],
                       fmaf(a1, wxr[1][j], fmaf(a2, wxr[2][j], brr[j])));
        }
        float4 o0 = make_float4(acc[0], acc[1], acc[2], acc[3]);
        float4 o1 = make_float4(acc[4], acc[5], acc[6], acc[7]);
        ((float4*)C)[(size_t)row * 16 + tx * 2 + 0] = o0;
        ((float4*)C)[(size_t)row * 16 + tx * 2 + 1] = o1;
    }
}

// intermediate variant: fp16-only output (consumed solely by fp16 gather)
__global__ void k_mm96h(const float* __restrict__ A, const float* __restrict__ W,
                        uint4* __restrict__ C16, int N) {
    __shared__ float As[96][65];
    __shared__ float Ws[64][64];
    int tid = threadIdx.x;
    int row0 = blockIdx.x * 96;
    {
        const float4* Wv = (const float4*)W;
        float4* Wsv = (float4*)Ws;
        for (int i = tid; i < 1024; i += 96) Wsv[i] = Wv[i];
    }
    for (int i = tid; i < 96 * 16; i += 96) {
        int r = i >> 4, kq = i & 15;
        int row = row0 + r;
        float4 v = make_float4(0.f, 0.f, 0.f, 0.f);
        if (row < N) v = ((const float4*)A)[(size_t)row * 16 + kq];
        As[r][kq * 4 + 0] = v.x;
        As[r][kq * 4 + 1] = v.y;
        As[r][kq * 4 + 2] = v.z;
        As[r][kq * 4 + 3] = v.w;
    }
    __syncthreads();

    int tx = tid & 7, ty = tid >> 3;
    u64 acc2[8][4];
#pragma unroll
    for (int i = 0; i < 8; i++)
#pragma unroll
        for (int j = 0; j < 4; j++) acc2[i][j] = 0ull;

#pragma unroll 8
    for (int k = 0; k < 64; k++) {
        u64 ad[8];
#pragma unroll
        for (int i = 0; i < 8; i++) {
            float a = As[ty * 8 + i][k];
            ad[i] = pack2(a, a);
        }
        const u64* wp = (const u64*)&Ws[k][tx * 8];
        u64 w0 = wp[0], w1 = wp[1], w2 = wp[2], w3 = wp[3];
#pragma unroll
        for (int i = 0; i < 8; i++) {
            ffma2(acc2[i][0], ad[i], w0);
            ffma2(acc2[i][1], ad[i], w1);
            ffma2(acc2[i][2], ad[i], w2);
            ffma2(acc2[i][3], ad[i], w3);
        }
    }

#pragma unroll
    for (int i = 0; i < 8; i++) {
        int row = row0 + ty * 8 + i;
        if (row >= N) continue;
        float acc[8];
#pragma unroll
        for (int j = 0; j < 4; j++) unpack2(acc2[i][j], acc[2 * j], acc[2 * j + 1]);
        uint4 o16;
        o16.x = f2h(acc[0], acc[1]);
        o16.y = f2h(acc[2], acc[3]);
        o16.z = f2h(acc[4], acc[5]);
        o16.w = f2h(acc[6], acc[7]);
        C16[(size_t)row * 8 + tx] = o16;
    }
}

// small head matmuls: warp per node
template <int FIN, int FOUT>
__global__ void k_mm_small(const float* __restrict__ A, const float* __restrict__ W,
                           float* __restrict__ C, int N) {
    __shared__ float Ws[FIN * FOUT + 32];
    int tid = threadIdx.x;
    for (int i = tid; i < FIN * FOUT; i += blockDim.x) Ws[i] = W[i];
    for (int i = FIN * FOUT + tid; i < FIN * FOUT + 32; i += blockDim.x) Ws[i] = 0.f;
    __syncthreads();
    int node = blockIdx.x * 4 + (tid >> 5);
    int j = tid & 31;
    if (node >= N) return;
    float acc = 0.f;
    const float* a = A + (size_t)node * FIN;
#pragma unroll
    for (int k = 0; k < FIN; k++) {
        float av = __ldg(a + k);
        acc = fmaf(av, Ws[k * FOUT + j], acc);
    }
    if (j < FOUT) C[(size_t)node * FOUT + j] = acc;
}

// =============== host launch ===============

extern "C" void kernel_launch(void* const* d_in, const int* in_sizes, int n_in,
                              void* d_out, int out_size) {
    const float* x   = (const float*)d_in[0];
    const float* Wp  = (const float*)d_in[1];
    const float* bp  = (const float*)d_in[2];
    const float* Wr  = (const float*)d_in[3];
    const float* br  = (const float*)d_in[4];
    const float* W11 = (const float*)d_in[5];
    const float* b11 = (const float*)d_in[6];
    const float* W12 = (const float*)d_in[7];
    const float* b12 = (const float*)d_in[8];
    const float* W21 = (const float*)d_in[9];
    const float* b21 = (const float*)d_in[10];
    const float* W22 = (const float*)d_in[11];
    const float* b22 = (const float*)d_in[12];
    const float* Wh1 = (const float*)d_in[13];
    const float* bh1 = (const float*)d_in[14];
    const float* Wh2 = (const float*)d_in[15];
    const float* bh2 = (const float*)d_in[16];
    const float* Wh3 = (const float*)d_in[17];
    const float* bh3 = (const float*)d_in[18];
    const int*   ei  = (const int*)d_in[19];

    int N = in_sizes[0] / 3;
    int E = in_sizes[19] / 2;
    const int* esrc = ei;
    const int* edst = ei + E;

    int *counts, *rowoff, *bsums;
    float *dis, *aggx;
    EdgeRec* edges;
    float4 *t4, *u4, *v4;
    uint4 *t16p, *u16p;
    cudaGetSymbolAddress((void**)&counts, g_counts);
    cudaGetSymbolAddress((void**)&rowoff, g_rowoff);
    cudaGetSymbolAddress((void**)&bsums, g_bsums);
    cudaGetSymbolAddress((void**)&dis, g_dis);
    cudaGetSymbolAddress((void**)&edges, g_edges);
    cudaGetSymbolAddress((void**)&aggx, g_aggx);
    cudaGetSymbolAddress((void**)&t4, g_t);
    cudaGetSymbolAddress((void**)&u4, g_u);
    cudaGetSymbolAddress((void**)&v4, g_v);
    cudaGetSymbolAddress((void**)&t16p, g_t16);
    cudaGetSymbolAddress((void**)&u16p, g_u16);
    float* t = (float*)t4;
    float* u = (float*)u4;
    float* v = (float*)v4;
    u32* t16 = (u32*)t16p;
    u32* u16 = (u32*)u16p;

    int nbE = (E + 255) / 256;
    int nbN = (N + 255) / 256;
    int nbScan = (N + 511) / 512;
    int nbWarp = (N + 7) / 8;       // 8 nodes per 256-thread block
    int nbMM = (N + 95) / 96;
    int nbW4 = (N + 3) / 4;

    // ---- graph setup ----
    cudaMemsetAsync(counts, 0, (size_t)N * sizeof(int), 0);
    k_count<<<nbE, 256>>>(edst, E, counts);
    k_dis<<<nbN, 256>>>(counts, dis, N);
    k_scan1<<<nbScan, 512>>>(counts, rowoff, bsums, N);
    k_scan2<<<1, 256>>>(bsums, nbScan);
    k_scan3<<<nbScan, 512>>>(rowoff, bsums, N, E);
    cudaMemsetAsync(counts, 0, (size_t)N * sizeof(int), 0);
    k_fill<<<nbE, 256>>>(esrc, edst, E, rowoff, counts, dis, edges);

    // ---- loop-invariant: agg(x) and projection ----
    k_agg_t<3><<<nbN, 256>>>(x, edges, rowoff, dis, nullptr, 0, aggx, N);
    k_proj<<<nbW4, 256>>>(aggx, Wp, bp, t, t16, N);

    const float* Wrx = Wr + 64 * 64;  // rows 64..66 of Wr (x part)

    // ---- iterations ----
    for (int it = 0; it < ITERS; it++) {
        // recall: v = agg(t)   [gathers t16];  t = v@Wr_t + aggx@Wr_x + br
        k_agg64h<0, 0, 0><<<nbWarp, 256>>>(t16, edges, rowoff, dis,
                                           nullptr, nullptr, v, nullptr, N);
        k_mm96<<<nbMM, 96>>>(v, Wr, Wrx, br, aggx, t, N);
        // block 1
        k_mm96h<<<nbMM, 96>>>(t, W11, u16p, N);
        k_agg64h<1, 0, 0><<<nbWarp, 256>>>(u16, edges, rowoff, dis,
                                           b11, nullptr, v, nullptr, N);
        k_mm96h<<<nbMM, 96>>>(v, W12, u16p, N);
        k_agg64h<1, 1, 1><<<nbWarp, 256>>>(u16, edges, rowoff, dis,
                                           b12, t, t, t16, N);
        // block 2
        k_mm96h<<<nbMM, 96>>>(t, W21, u16p, N);
        k_agg64h<1, 0, 0><<<nbWarp, 256>>>(u16, edges, rowoff, dis,
                                           b21, nullptr, v, nullptr, N);
        k_mm96h<<<nbMM, 96>>>(v, W22, u16p, N);
        k_agg64h<1, 1, 1><<<nbWarp, 256>>>(u16, edges, rowoff, dis,
                                           b22, t, t, t16, N);
    }

    // ---- head (fp32 throughout) ----
    k_mm_small<64, 32><<<nbW4, 128>>>(t, Wh1, u, N);
    k_agg32<<<nbWarp, 256>>>(u, edges, rowoff, dis, bh1, 1, v, N);
    k_mm_small<32, 8><<<nbW4, 128>>>(v, Wh2, u, N);
    k_agg_t<8><<<nbN, 256>>>(u, edges, rowoff, dis, bh2, 1, v, N);
    k_mm_small<8, 2><<<nbW4, 128>>>(v, Wh3, u, N);
    k_agg_t<2><<<nbN, 256>>>(u, edges, rowoff, dis, bh3, 0, (float*)d_out, N);
}

// round 8
// speedup vs baseline: 2.4398x; 1.0391x over previous
#include <cuda_runtime.h>
#include <cuda_fp16.h>
#include <math.h>

// Problem-fixed capacities (dataset constants)
#define NCAP 100000
#define ECAP 1600000
#define ITERS 5

struct __align__(8) EdgeRec { int src; float w; };
typedef unsigned long long u64;
typedef unsigned int u32;

// ---- static device scratch (no allocation allowed) ----
__device__ int     g_counts[NCAP];
__device__ int     g_cursor[NCAP];
__device__ int     g_rowoff[NCAP];
__device__ int     g_rowend[NCAP];
__device__ int     g_total[4];
__device__ float   g_dis[NCAP];
__device__ EdgeRec g_edges[ECAP];
__device__ float   g_aggx[NCAP * 3];
// float4-typed to guarantee 16B alignment for vector loads
__device__ float4  g_t[NCAP * 16];
__device__ float4  g_u[NCAP * 16];
__device__ float4  g_v[NCAP * 16];
// fp16 mirrors (64 halfs = 16 uint2 per node)
__device__ uint4   g_t16[NCAP * 8];
__device__ uint4   g_u16[NCAP * 8];

// ---- packed fp32x2 helpers (Blackwell FFMA2 path) ----
__device__ __forceinline__ u64 pack2(float x, float y) {
    u64 r; asm("mov.b64 %0, {%1, %2};" : "=l"(r) : "f"(x), "f"(y)); return r;
}
__device__ __forceinline__ void unpack2(u64 v, float& x, float& y) {
    asm("mov.b64 {%0, %1}, %2;" : "=f"(x), "=f"(y) : "l"(v));
}
__device__ __forceinline__ void ffma2(u64& d, u64 a, u64 b) {
    asm("fma.rn.f32x2 %0, %1, %2, %0;" : "+l"(d) : "l"(a), "l"(b));
}

// ---- fp16 pack/unpack ----
__device__ __forceinline__ float2 h2f(u32 q) {
    __half2 h = *reinterpret_cast<__half2*>(&q);
    return __half22float2(h);
}
__device__ __forceinline__ u32 f2h(float x, float y) {
    __half2 h = __floats2half2_rn(x, y);
    return *reinterpret_cast<u32*>(&h);
}

// =============== graph setup kernels ===============

__global__ void k_count(const int* __restrict__ dst, int E, int* __restrict__ counts) {
    int i = blockIdx.x * blockDim.x + threadIdx.x;
    if (i < E) atomicAdd(&counts[dst[i]], 1);
}

__global__ void k_dis(const int* __restrict__ counts, float* __restrict__ dis, int N) {
    int i = blockIdx.x * blockDim.x + threadIdx.x;
    if (i < N) dis[i] = rsqrtf((float)(counts[i] + 1));   // +1 self loop
}

// segment allocator: unordered CSR offsets via atomicAdd (valid partition)
__global__ void k_alloc(const int* __restrict__ counts, int* __restrict__ rowoff,
                        int* __restrict__ rowend, int* __restrict__ total, int N) {
    int i = blockIdx.x * blockDim.x + threadIdx.x;
    if (i >= N) return;
    int c = counts[i];
    int off = atomicAdd(total, c);
    rowoff[i] = off;
    rowend[i] = off + c;
}

__global__ void k_fill(const int* __restrict__ srcA, const int* __restrict__ dstA, int E,
                       const int* __restrict__ rowoff, int* __restrict__ cursor,
                       const float* __restrict__ dis, EdgeRec* __restrict__ edges) {
    int i = blockIdx.x * blockDim.x + threadIdx.x;
    if (i >= E) return;
    int s = srcA[i], d = dstA[i];
    int pos = rowoff[d] + atomicAdd(&cursor[d], 1);
    EdgeRec r;
    r.src = s;
    r.w = dis[s] * dis[d];
    edges[pos] = r;
}

// =============== aggregation kernels ===============

// width-64 fp16-gather v2: half-warp per node (16 lanes x uint2 = 64 halfs),
// 2 nodes per warp -> 1 feature-LDG instr serves 2 edges. 4-edge unroll.
template <int RELU, int RES, int MIRROR>
__global__ void k_aggv(const uint2* __restrict__ U16, const EdgeRec* __restrict__ edges,
                       const int* __restrict__ rowoff, const int* __restrict__ rowend,
                       const float* __restrict__ dis,
                       const float* __restrict__ bias, const float* __restrict__ res,
                       float* __restrict__ out, uint2* __restrict__ out16, int N) {
    int tid = threadIdx.x;
    int warp = tid >> 5;
    int half = (tid >> 4) & 1;
    int sub = tid & 15;
    int node = blockIdx.x * 16 + warp * 2 + half;
    if (node >= N) return;

    float ac0[4] = {0.f, 0.f, 0.f, 0.f};
    float ac1[4] = {0.f, 0.f, 0.f, 0.f};
    float ac2[4] = {0.f, 0.f, 0.f, 0.f};
    float ac3[4] = {0.f, 0.f, 0.f, 0.f};

    int e = rowoff[node];
    int e1 = rowend[node];
    for (; e + 4 <= e1; e += 4) {
        u64 er0 = *(const u64*)(edges + e);
        u64 er1 = *(const u64*)(edges + e + 1);
        u64 er2 = *(const u64*)(edges + e + 2);
        u64 er3 = *(const u64*)(edges + e + 3);
        int s0 = (int)(u32)er0; float w0 = __uint_as_float((u32)(er0 >> 32));
        int s1 = (int)(u32)er1; float w1 = __uint_as_float((u32)(er1 >> 32));
        int s2 = (int)(u32)er2; float w2 = __uint_as_float((u32)(er2 >> 32));
        int s3 = (int)(u32)er3; float w3 = __uint_as_float((u32)(er3 >> 32));
        uint2 q0 = U16[(size_t)s0 * 16 + sub];
        uint2 q1 = U16[(size_t)s1 * 16 + sub];
        uint2 q2 = U16[(size_t)s2 * 16 + sub];
        uint2 q3 = U16[(size_t)s3 * 16 + sub];
        float2 f0a = h2f(q0.x), f0b = h2f(q0.y);
        float2 f1a = h2f(q1.x), f1b = h2f(q1.y);
        float2 f2a = h2f(q2.x), f2b = h2f(q2.y);
        float2 f3a = h2f(q3.x), f3b = h2f(q3.y);
        ac0[0] = fmaf(w0, f0a.x, ac0[0]); ac0[1] = fmaf(w0, f0a.y, ac0[1]);
        ac0[2] = fmaf(w0, f0b.x, ac0[2]); ac0[3] = fmaf(w0, f0b.y, ac0[3]);
        ac1[0] = fmaf(w1, f1a.x, ac1[0]); ac1[1] = fmaf(w1, f1a.y, ac1[1]);
        ac1[2] = fmaf(w1, f1b.x, ac1[2]); ac1[3] = fmaf(w1, f1b.y, ac1[3]);
        ac2[0] = fmaf(w2, f2a.x, ac2[0]); ac2[1] = fmaf(w2, f2a.y, ac2[1]);
        ac2[2] = fmaf(w2, f2b.x, ac2[2]); ac2[3] = fmaf(w2, f2b.y, ac2[3]);
        ac3[0] = fmaf(w3, f3a.x, ac3[0]); ac3[1] = fmaf(w3, f3a.y, ac3[1]);
        ac3[2] = fmaf(w3, f3b.x, ac3[2]); ac3[3] = fmaf(w3, f3b.y, ac3[3]);
    }
    for (; e < e1; e++) {
        u64 er = *(const u64*)(edges + e);
        int s = (int)(u32)er; float w = __uint_as_float((u32)(er >> 32));
        uint2 q = U16[(size_t)s * 16 + sub];
        float2 fa = h2f(q.x), fb = h2f(q.y);
        ac0[0] = fmaf(w, fa.x, ac0[0]); ac0[1] = fmaf(w, fa.y, ac0[1]);
        ac0[2] = fmaf(w, fb.x, ac0[2]); ac0[3] = fmaf(w, fb.y, ac0[3]);
    }
    // self loop
    {
        float dv = dis[node];
        float sw = dv * dv;
        uint2 q = U16[(size_t)node * 16 + sub];
        float2 fa = h2f(q.x), fb = h2f(q.y);
        ac1[0] = fmaf(sw, fa.x, ac1[0]); ac1[1] = fmaf(sw, fa.y, ac1[1]);
        ac1[2] = fmaf(sw, fb.x, ac1[2]); ac1[3] = fmaf(sw, fb.y, ac1[3]);
    }
    float4 o;
    o.x = (ac0[0] + ac1[0]) + (ac2[0] + ac3[0]);
    o.y = (ac0[1] + ac1[1]) + (ac2[1] + ac3[1]);
    o.z = (ac0[2] + ac1[2]) + (ac2[2] + ac3[2]);
    o.w = (ac0[3] + ac1[3]) + (ac2[3] + ac3[3]);
    if (bias) {
        float4 b = ((const float4*)bias)[sub];
        o.x += b.x; o.y += b.y; o.z += b.z; o.w += b.w;
    }
    if (RES) {
        float4 rr = ((const float4*)res)[(size_t)node * 16 + sub];
        o.x += rr.x; o.y += rr.y; o.z += rr.z; o.w += rr.w;
    }
    if (RELU) {
        o.x = fmaxf(o.x, 0.f); o.y = fmaxf(o.y, 0.f);
        o.z = fmaxf(o.z, 0.f); o.w = fmaxf(o.w, 0.f);
    }
    ((float4*)out)[(size_t)node * 16 + sub] = o;
    if (MIRROR) {
        uint2 m;
        m.x = f2h(o.x, o.y);
        m.y = f2h(o.z, o.w);
        out16[(size_t)node * 16 + sub] = m;
    }
}

// width-32 fp32: warp per node (head)
__global__ void k_agg32(const float* __restrict__ u, const EdgeRec* __restrict__ edges,
                        const int* __restrict__ rowoff, const int* __restrict__ rowend,
                        const float* __restrict__ dis,
                        const float* __restrict__ bias, int relu,
                        float* __restrict__ out, int N) {
    int node = blockIdx.x * 8 + (threadIdx.x >> 5);
    int lane = threadIdx.x & 31;
    if (node >= N) return;
    float acc = 0.f;
    int e0 = rowoff[node], e1 = rowend[node];
    for (int e = e0; e < e1; e++) {
        EdgeRec r = edges[e];
        acc = fmaf(r.w, u[(size_t)r.src * 32 + lane], acc);
    }
    float dv = dis[node];
    acc = fmaf(dv * dv, u[(size_t)node * 32 + lane], acc);
    if (bias) acc += bias[lane];
    if (relu) acc = fmaxf(acc, 0.f);
    out[(size_t)node * 32 + lane] = acc;
}

// small widths (2,3,8): thread per node
template <int W>
__global__ void k_agg_t(const float* __restrict__ u, const EdgeRec* __restrict__ edges,
                        const int* __restrict__ rowoff, const int* __restrict__ rowend,
                        const float* __restrict__ dis,
                        const float* __restrict__ bias, int relu,
                        float* __restrict__ out, int N) {
    int node = blockIdx.x * blockDim.x + threadIdx.x;
    if (node >= N) return;
    float acc[W];
#pragma unroll
    for (int k = 0; k < W; k++) acc[k] = 0.f;
    int e0 = rowoff[node], e1 = rowend[node];
    for (int e = e0; e < e1; e++) {
        EdgeRec r = edges[e];
        const float* up = u + (size_t)r.src * W;
#pragma unroll
        for (int k = 0; k < W; k++) acc[k] = fmaf(r.w, __ldg(up + k), acc[k]);
    }
    float dv = dis[node];
    float sw = dv * dv;
    const float* us = u + (size_t)node * W;
#pragma unroll
    for (int k = 0; k < W; k++) acc[k] = fmaf(sw, us[k], acc[k]);
    if (bias) {
#pragma unroll
        for (int k = 0; k < W; k++) acc[k] += bias[k];
    }
    if (relu) {
#pragma unroll
        for (int k = 0; k < W; k++) acc[k] = fmaxf(acc[k], 0.f);
    }
#pragma unroll
    for (int k = 0; k < W; k++) out[(size_t)node * W + k] = acc[k];
}

// =============== dense kernels ===============

// projection: t = relu(aggx @ Wp + bp), fp32 + fp16 mirror
__global__ void k_proj(const float* __restrict__ aggx, const float* __restrict__ Wp,
                       const float* __restrict__ bp, float* __restrict__ t,
                       u32* __restrict__ t16, int N) {
    int node = blockIdx.x * 4 + (threadIdx.x >> 6);
    int j = threadIdx.x & 63;
    if (node >= N) return;
    float a0 = aggx[node * 3], a1 = aggx[node * 3 + 1], a2 = aggx[node * 3 + 2];
    float acc = bp[j];
    acc = fmaf(a0, Wp[j], acc);
    acc = fmaf(a1, Wp[64 + j], acc);
    acc = fmaf(a2, Wp[128 + j], acc);
    acc = fmaxf(acc, 0.f);
    t[(size_t)node * 64 + j] = acc;
    ((__half*)t16)[(size_t)node * 64 + j] = __float2half_rn(acc);
}

// recall matmul: C = A@Wr_t + aggx@Wr_x + br (fp32 out)
__global__ void k_mm96(const float* __restrict__ A, const float* __restrict__ W,
                       const float* __restrict__ Wx, const float* __restrict__ brv,
                       const float* __restrict__ aggx, float* __restrict__ C, int N) {
    __shared__ float As[96][65];
    __shared__ float Ws[64][64];
    int tid = threadIdx.x;
    int row0 = blockIdx.x * 96;
    {
        const float4* Wv = (const float4*)W;
        float4* Wsv = (float4*)Ws;
        for (int i = tid; i < 1024; i += 96) Wsv[i] = Wv[i];
    }
    for (int i = tid; i < 96 * 16; i += 96) {
        int r = i >> 4, kq = i & 15;
        int row = row0 + r;
        float4 v = make_float4(0.f, 0.f, 0.f, 0.f);
        if (row < N) v = ((const float4*)A)[(size_t)row * 16 + kq];
        As[r][kq * 4 + 0] = v.x;
        As[r][kq * 4 + 1] = v.y;
        As[r][kq * 4 + 2] = v.z;
        As[r][kq * 4 + 3] = v.w;
    }
    __syncthreads();

    int tx = tid & 7, ty = tid >> 3;
    u64 acc2[8][4];
#pragma unroll
    for (int i = 0; i < 8; i++)
#pragma unroll
        for (int j = 0; j < 4; j++) acc2[i][j] = 0ull;

#pragma unroll 8
    for (int k = 0; k < 64; k++) {
        u64 ad[8];
#pragma unroll
        for (int i = 0; i < 8; i++) {
            float a = As[ty * 8 + i][k];
            ad[i] = pack2(a, a);
        }
        const u64* wp = (const u64*)&Ws[k][tx * 8];
        u64 w0 = wp[0], w1 = wp[1], w2 = wp[2], w3 = wp[3];
#pragma unroll
        for (int i = 0; i < 8; i++) {
            ffma2(acc2[i][0], ad[i], w0);
            ffma2(acc2[i][1], ad[i], w1);
            ffma2(acc2[i][2], ad[i], w2);
            ffma2(acc2[i][3], ad[i], w3);
        }
    }

    float wxr[3][8], brr[8];
#pragma unroll
    for (int j = 0; j < 8; j++) {
        int col = tx * 8 + j;
        wxr[0][j] = Wx[col];
        wxr[1][j] = Wx[64 + col];
        wxr[2][j] = Wx[128 + col];
        brr[j] = brv[col];
    }
#pragma unroll
    for (int i = 0; i < 8; i++) {
        int row = row0 + ty * 8 + i;
        if (row >= N) continue;
        float acc[8];
#pragma unroll
        for (int j = 0; j < 4; j++) unpack2(acc2[i][j], acc[2 * j], acc[2 * j + 1]);
        float a0 = aggx[row * 3], a1 = aggx[row * 3 + 1], a2 = aggx[row * 3 + 2];
#pragma unroll
        for (int j = 0; j < 8; j++) {
            acc[j] += fmaf(a0, wxr[0][j],
                       fmaf(a1, wxr[1][j], fmaf(a2, wxr[2][j], brr[j])));
        }
        float4 o0 = make_float4(acc[0], acc[1], acc[2], acc[3]);
        float4 o1 = make_float4(acc[4], acc[5], acc[6], acc[7]);
        ((float4*)C)[(size_t)row * 16 + tx * 2 + 0] = o0;
        ((float4*)C)[(size_t)row * 16 + tx * 2 + 1] = o1;
    }
}

// intermediate variant: fp16-only output (consumed solely by fp16 gather)
__global__ void k_mm96h(const float* __restrict__ A, const float* __restrict__ W,
                        uint4* __restrict__ C16, int N) {
    __shared__ float As[96][65];
    __shared__ float Ws[64][64];
    int tid = threadIdx.x;
    int row0 = blockIdx.x * 96;
    {
        const float4* Wv = (const float4*)W;
        float4* Wsv = (float4*)Ws;
        for (int i = tid; i < 1024; i += 96) Wsv[i] = Wv[i];
    }
    for (int i = tid; i < 96 * 16; i += 96) {
        int r = i >> 4, kq = i & 15;
        int row = row0 + r;
        float4 v = make_float4(0.f, 0.f, 0.f, 0.f);
        if (row < N) v = ((const float4*)A)[(size_t)row * 16 + kq];
        As[r][kq * 4 + 0] = v.x;
        As[r][kq * 4 + 1] = v.y;
        As[r][kq * 4 + 2] = v.z;
        As[r][kq * 4 + 3] = v.w;
    }
    __syncthreads();

    int tx = tid & 7, ty = tid >> 3;
    u64 acc2[8][4];
#pragma unroll
    for (int i = 0; i < 8; i++)
#pragma unroll
        for (int j = 0; j < 4; j++) acc2[i][j] = 0ull;

#pragma unroll 8
    for (int k = 0; k < 64; k++) {
        u64 ad[8];
#pragma unroll
        for (int i = 0; i < 8; i++) {
            float a = As[ty * 8 + i][k];
            ad[i] = pack2(a, a);
        }
        const u64* wp = (const u64*)&Ws[k][tx * 8];
        u64 w0 = wp[0], w1 = wp[1], w2 = wp[2], w3 = wp[3];
#pragma unroll
        for (int i = 0; i < 8; i++) {
            ffma2(acc2[i][0], ad[i], w0);
            ffma2(acc2[i][1], ad[i], w1);
            ffma2(acc2[i][2], ad[i], w2);
            ffma2(acc2[i][3], ad[i], w3);
        }
    }

#pragma unroll
    for (int i = 0; i < 8; i++) {
        int row = row0 + ty * 8 + i;
        if (row >= N) continue;
        float acc[8];
#pragma unroll
        for (int j = 0; j < 4; j++) unpack2(acc2[i][j], acc[2 * j], acc[2 * j + 1]);
        uint4 o16;
        o16.x = f2h(acc[0], acc[1]);
        o16.y = f2h(acc[2], acc[3]);
        o16.z = f2h(acc[4], acc[5]);
        o16.w = f2h(acc[6], acc[7]);
        C16[(size_t)row * 8 + tx] = o16;
    }
}

// small head matmuls: warp per node
template <int FIN, int FOUT>
__global__ void k_mm_small(const float* __restrict__ A, const float* __restrict__ W,
                           float* __restrict__ C, int N) {
    __shared__ float Ws[FIN * FOUT + 32];
    int tid = threadIdx.x;
    for (int i = tid; i < FIN * FOUT; i += blockDim.x) Ws[i] = W[i];
    for (int i = FIN * FOUT + tid; i < FIN * FOUT + 32; i += blockDim.x) Ws[i] = 0.f;
    __syncthreads();
    int node = blockIdx.x * 4 + (tid >> 5);
    int j = tid & 31;
    if (node >= N) return;
    float acc = 0.f;
    const float* a = A + (size_t)node * FIN;
#pragma unroll
    for (int k = 0; k < FIN; k++) {
        float av = __ldg(a + k);
        acc = fmaf(av, Ws[k * FOUT + j], acc);
    }
    if (j < FOUT) C[(size_t)node * FOUT + j] = acc;
}

// =============== host launch ===============

extern "C" void kernel_launch(void* const* d_in, const int* in_sizes, int n_in,
                              void* d_out, int out_size) {
    const float* x   = (const float*)d_in[0];
    const float* Wp  = (const float*)d_in[1];
    const float* bp  = (const float*)d_in[2];
    const float* Wr  = (const float*)d_in[3];
    const float* br  = (const float*)d_in[4];
    const float* W11 = (const float*)d_in[5];
    const float* b11 = (const float*)d_in[6];
    const float* W12 = (const float*)d_in[7];
    const float* b12 = (const float*)d_in[8];
    const float* W21 = (const float*)d_in[9];
    const float* b21 = (const float*)d_in[10];
    const float* W22 = (const float*)d_in[11];
    const float* b22 = (const float*)d_in[12];
    const float* Wh1 = (const float*)d_in[13];
    const float* bh1 = (const float*)d_in[14];
    const float* Wh2 = (const float*)d_in[15];
    const float* bh2 = (const float*)d_in[16];
    const float* Wh3 = (const float*)d_in[17];
    const float* bh3 = (const float*)d_in[18];
    const int*   ei  = (const int*)d_in[19];

    int N = in_sizes[0] / 3;
    int E = in_sizes[19] / 2;
    const int* esrc = ei;
    const int* edst = ei + E;

    int *counts, *cursor, *rowoff, *rowend, *total;
    float *dis, *aggx;
    EdgeRec* edges;
    float4 *t4, *u4, *v4;
    uint4 *t16p, *u16p;
    cudaGetSymbolAddress((void**)&counts, g_counts);
    cudaGetSymbolAddress((void**)&cursor, g_cursor);
    cudaGetSymbolAddress((void**)&rowoff, g_rowoff);
    cudaGetSymbolAddress((void**)&rowend, g_rowend);
    cudaGetSymbolAddress((void**)&total, g_total);
    cudaGetSymbolAddress((void**)&dis, g_dis);
    cudaGetSymbolAddress((void**)&edges, g_edges);
    cudaGetSymbolAddress((void**)&aggx, g_aggx);
    cudaGetSymbolAddress((void**)&t4, g_t);
    cudaGetSymbolAddress((void**)&u4, g_u);
    cudaGetSymbolAddress((void**)&v4, g_v);
    cudaGetSymbolAddress((void**)&t16p, g_t16);
    cudaGetSymbolAddress((void**)&u16p, g_u16);
    float* t = (float*)t4;
    float* u = (float*)u4;
    float* v = (float*)v4;
    uint2* t16 = (uint2*)t16p;
    uint2* u16 = (uint2*)u16p;

    int nbE = (E + 255) / 256;
    int nbN = (N + 255) / 256;
    int nbWarp = (N + 7) / 8;       // 8 nodes per 256-thread block
    int nbAgg = (N + 15) / 16;      // 16 nodes per 256-thread block (half-warp)
    int nbMM = (N + 95) / 96;
    int nbW4 = (N + 3) / 4;

    // ---- graph setup ----
    cudaMemsetAsync(counts, 0, (size_t)N * sizeof(int), 0);
    cudaMemsetAsync(cursor, 0, (size_t)N * sizeof(int), 0);
    cudaMemsetAsync(total, 0, 4 * sizeof(int), 0);
    k_count<<<nbE, 256>>>(edst, E, counts);
    k_dis<<<nbN, 256>>>(counts, dis, N);
    k_alloc<<<nbN, 256>>>(counts, rowoff, rowend, total, N);
    k_fill<<<nbE, 256>>>(esrc, edst, E, rowoff, cursor, dis, edges);

    // ---- loop-invariant: agg(x) and projection ----
    k_agg_t<3><<<nbN, 256>>>(x, edges, rowoff, rowend, dis, nullptr, 0, aggx, N);
    k_proj<<<nbW4, 256>>>(aggx, Wp, bp, t, (u32*)t16, N);

    const float* Wrx = Wr + 64 * 64;  // rows 64..66 of Wr (x part)

    // ---- iterations ----
    for (int it = 0; it < ITERS; it++) {
        // recall: v = agg(t) [gathers t16]; t = v@Wr_t + aggx@Wr_x + br
        k_aggv<0, 0, 0><<<nbAgg, 256>>>(t16, edges, rowoff, rowend, dis,
                                        nullptr, nullptr, v, nullptr, N);
        k_mm96<<<nbMM, 96>>>(v, Wr, Wrx, br, aggx, t, N);
        // block 1
        k_mm96h<<<nbMM, 96>>>(t, W11, u16p, N);
        k_aggv<1, 0, 0><<<nbAgg, 256>>>(u16, edges, rowoff, rowend, dis,
                                        b11, nullptr, v, nullptr, N);
        k_mm96h<<<nbMM, 96>>>(v, W12, u16p, N);
        k_aggv<1, 1, 1><<<nbAgg, 256>>>(u16, edges, rowoff, rowend, dis,
                                        b12, t, t, t16, N);
        // block 2
        k_mm96h<<<nbMM, 96>>>(t, W21, u16p, N);
        k_aggv<1, 0, 0><<<nbAgg, 256>>>(u16, edges, rowoff, rowend, dis,
                                        b21, nullptr, v, nullptr, N);
        k_mm96h<<<nbMM, 96>>>(v, W22, u16p, N);
        k_aggv<1, 1, 1><<<nbAgg, 256>>>(u16, edges, rowoff, rowend, dis,
                                        b22, t, t, t16, N);
    }

    // ---- head (fp32 throughout) ----
    k_mm_small<64, 32><<<nbW4, 128>>>(t, Wh1, u, N);
    k_agg32<<<nbWarp, 256>>>(u, edges, rowoff, rowend, dis, bh1, 1, v, N);
    k_mm_small<32, 8><<<nbW4, 128>>>(v, Wh2, u, N);
    k_agg_t<8><<<nbN, 256>>>(u, edges, rowoff, rowend, dis, bh2, 1, v, N);
    k_mm_small<8, 2><<<nbW4, 128>>>(v, Wh3, u, N);
    k_agg_t<2><<<nbN, 256>>>(u, edges, rowoff, rowend, dis, bh3, 0, (float*)d_out, N);
}

// round 9
// speedup vs baseline: 2.6718x; 1.0951x over previous
#include <cuda_runtime.h>
#include <cuda_fp16.h>
#include <mma.h>
#include <math.h>

using namespace nvcuda;

// Problem-fixed capacities (dataset constants)
#define NCAP 100000
#define NPAD (NCAP + 128)
#define ECAP 1600000
#define ITERS 5

struct __align__(8) EdgeRec { int src; float w; };
typedef unsigned long long u64;
typedef unsigned int u32;

// ---- static device scratch (no allocation allowed) ----
__device__ int     g_counts[NCAP];
__device__ int     g_cursor[NCAP];
__device__ int     g_rowoff[NCAP];
__device__ int     g_rowend[NCAP];
__device__ int     g_total[4];
__device__ float   g_dis[NCAP];
__device__ EdgeRec g_edges[ECAP];
__device__ float   g_aggx[NCAP * 3];
__device__ float4  g_t[NCAP * 16];
__device__ float4  g_u[NCAP * 16];
__device__ float4  g_v[NCAP * 16];
// fp16 mirrors, padded to NPAD rows (64 halfs = 8 uint4 per node)
__device__ uint4   g_t16[NPAD * 8];
__device__ uint4   g_u16[NPAD * 8];
__device__ uint4   g_v16[NPAD * 8];
// fp16 weights: Wr_t, W11, W12, W21, W22 (each 64x64)
__device__ uint4   g_w16[5 * 4096 / 8];

// ---- fp16 pack/unpack ----
__device__ __forceinline__ float2 h2f(u32 q) {
    __half2 h = *reinterpret_cast<__half2*>(&q);
    return __half22float2(h);
}
__device__ __forceinline__ u32 f2h(float x, float y) {
    __half2 h = __floats2half2_rn(x, y);
    return *reinterpret_cast<u32*>(&h);
}

// =============== graph setup kernels ===============

__global__ void k_count(const int* __restrict__ dst, int E, int* __restrict__ counts) {
    int i = blockIdx.x * blockDim.x + threadIdx.x;
    if (i < E) atomicAdd(&counts[dst[i]], 1);
}

__global__ void k_dis(const int* __restrict__ counts, float* __restrict__ dis, int N) {
    int i = blockIdx.x * blockDim.x + threadIdx.x;
    if (i < N) dis[i] = rsqrtf((float)(counts[i] + 1));   // +1 self loop
}

// segment allocator: unordered CSR offsets via atomicAdd (valid partition)
__global__ void k_alloc(const int* __restrict__ counts, int* __restrict__ rowoff,
                        int* __restrict__ rowend, int* __restrict__ total, int N) {
    int i = blockIdx.x * blockDim.x + threadIdx.x;
    if (i >= N) return;
    int c = counts[i];
    int off = atomicAdd(total, c);
    rowoff[i] = off;
    rowend[i] = off + c;
}

__global__ void k_fill(const int* __restrict__ srcA, const int* __restrict__ dstA, int E,
                       const int* __restrict__ rowoff, int* __restrict__ cursor,
                       const float* __restrict__ dis, EdgeRec* __restrict__ edges) {
    int i = blockIdx.x * blockDim.x + threadIdx.x;
    if (i >= E) return;
    int s = srcA[i], d = dstA[i];
    int pos = rowoff[d] + atomicAdd(&cursor[d], 1);
    EdgeRec r;
    r.src = s;
    r.w = dis[s] * dis[d];
    edges[pos] = r;
}

// convert weights to fp16 (Wr_t = first 64 rows of Wr, plus 4 block weights)
__global__ void k_cvtW(const float* __restrict__ Wr, const float* __restrict__ W11,
                       const float* __restrict__ W12, const float* __restrict__ W21,
                       const float* __restrict__ W22, __half* __restrict__ out) {
    int i = blockIdx.x * blockDim.x + threadIdx.x;
    if (i >= 4096) return;
    out[i]            = __float2half_rn(Wr[i]);
    out[4096 + i]     = __float2half_rn(W11[i]);
    out[2 * 4096 + i] = __float2half_rn(W12[i]);
    out[3 * 4096 + i] = __float2half_rn(W21[i]);
    out[4 * 4096 + i] = __float2half_rn(W22[i]);
}

// =============== aggregation kernels ===============

// width-64 fp16-gather: half-warp per node (16 lanes x uint2 = 64 halfs),
// 2 nodes per warp. fp32 accumulate. Always writes fp16 out; fp32 if W32.
template <int RELU, int RES, int W32>
__global__ void k_aggv(const uint2* __restrict__ U16, const EdgeRec* __restrict__ edges,
                       const int* __restrict__ rowoff, const int* __restrict__ rowend,
                       const float* __restrict__ dis,
                       const float* __restrict__ bias, const float* __restrict__ res,
                       float* __restrict__ out, uint2* __restrict__ out16, int N) {
    int tid = threadIdx.x;
    int warp = tid >> 5;
    int half = (tid >> 4) & 1;
    int sub = tid & 15;
    int node = blockIdx.x * 16 + warp * 2 + half;
    if (node >= N) return;

    float ac0[4] = {0.f, 0.f, 0.f, 0.f};
    float ac1[4] = {0.f, 0.f, 0.f, 0.f};
    float ac2[4] = {0.f, 0.f, 0.f, 0.f};
    float ac3[4] = {0.f, 0.f, 0.f, 0.f};

    int e = rowoff[node];
    int e1 = rowend[node];
    for (; e + 4 <= e1; e += 4) {
        u64 er0 = *(const u64*)(edges + e);
        u64 er1 = *(const u64*)(edges + e + 1);
        u64 er2 = *(const u64*)(edges + e + 2);
        u64 er3 = *(const u64*)(edges + e + 3);
        int s0 = (int)(u32)er0; float w0 = __uint_as_float((u32)(er0 >> 32));
        int s1 = (int)(u32)er1; float w1 = __uint_as_float((u32)(er1 >> 32));
        int s2 = (int)(u32)er2; float w2 = __uint_as_float((u32)(er2 >> 32));
        int s3 = (int)(u32)er3; float w3 = __uint_as_float((u32)(er3 >> 32));
        uint2 q0 = U16[(size_t)s0 * 16 + sub];
        uint2 q1 = U16[(size_t)s1 * 16 + sub];
        uint2 q2 = U16[(size_t)s2 * 16 + sub];
        uint2 q3 = U16[(size_t)s3 * 16 + sub];
        float2 f0a = h2f(q0.x), f0b = h2f(q0.y);
        float2 f1a = h2f(q1.x), f1b = h2f(q1.y);
        float2 f2a = h2f(q2.x), f2b = h2f(q2.y);
        float2 f3a = h2f(q3.x), f3b = h2f(q3.y);
        ac0[0] = fmaf(w0, f0a.x, ac0[0]); ac0[1] = fmaf(w0, f0a.y, ac0[1]);
        ac0[2] = fmaf(w0, f0b.x, ac0[2]); ac0[3] = fmaf(w0, f0b.y, ac0[3]);
        ac1[0] = fmaf(w1, f1a.x, ac1[0]); ac1[1] = fmaf(w1, f1a.y, ac1[1]);
        ac1[2] = fmaf(w1, f1b.x, ac1[2]); ac1[3] = fmaf(w1, f1b.y, ac1[3]);
        ac2[0] = fmaf(w2, f2a.x, ac2[0]); ac2[1] = fmaf(w2, f2a.y, ac2[1]);
        ac2[2] = fmaf(w2, f2b.x, ac2[2]); ac2[3] = fmaf(w2, f2b.y, ac2[3]);
        ac3[0] = fmaf(w3, f3a.x, ac3[0]); ac3[1] = fmaf(w3, f3a.y, ac3[1]);
        ac3[2] = fmaf(w3, f3b.x, ac3[2]); ac3[3] = fmaf(w3, f3b.y, ac3[3]);
    }
    for (; e < e1; e++) {
        u64 er = *(const u64*)(edges + e);
        int s = (int)(u32)er; float w = __uint_as_float((u32)(er >> 32));
        uint2 q = U16[(size_t)s * 16 + sub];
        float2 fa = h2f(q.x), fb = h2f(q.y);
        ac0[0] = fmaf(w, fa.x, ac0[0]); ac0[1] = fmaf(w, fa.y, ac0[1]);
        ac0[2] = fmaf(w, fb.x, ac0[2]); ac0[3] = fmaf(w, fb.y, ac0[3]);
    }
    // self loop
    {
        float dv = dis[node];
        float sw = dv * dv;
        uint2 q = U16[(size_t)node * 16 + sub];
        float2 fa = h2f(q.x), fb = h2f(q.y);
        ac1[0] = fmaf(sw, fa.x, ac1[0]); ac1[1] = fmaf(sw, fa.y, ac1[1]);
        ac1[2] = fmaf(sw, fb.x, ac1[2]); ac1[3] = fmaf(sw, fb.y, ac1[3]);
    }
    float4 o;
    o.x = (ac0[0] + ac1[0]) + (ac2[0] + ac3[0]);
    o.y = (ac0[1] + ac1[1]) + (ac2[1] + ac3[1]);
    o.z = (ac0[2] + ac1[2]) + (ac2[2] + ac3[2]);
    o.w = (ac0[3] + ac1[3]) + (ac2[3] + ac3[3]);
    if (bias) {
        float4 b = ((const float4*)bias)[sub];
        o.x += b.x; o.y += b.y; o.z += b.z; o.w += b.w;
    }
    if (RES) {
        float4 rr = ((const float4*)res)[(size_t)node * 16 + sub];
        o.x += rr.x; o.y += rr.y; o.z += rr.z; o.w += rr.w;
    }
    if (RELU) {
        o.x = fmaxf(o.x, 0.f); o.y = fmaxf(o.y, 0.f);
        o.z = fmaxf(o.z, 0.f); o.w = fmaxf(o.w, 0.f);
    }
    if (W32) ((float4*)out)[(size_t)node * 16 + sub] = o;
    {
        uint2 m;
        m.x = f2h(o.x, o.y);
        m.y = f2h(o.z, o.w);
        out16[(size_t)node * 16 + sub] = m;
    }
}

// width-32 fp32: warp per node (head)
__global__ void k_agg32(const float* __restrict__ u, const EdgeRec* __restrict__ edges,
                        const int* __restrict__ rowoff, const int* __restrict__ rowend,
                        const float* __restrict__ dis,
                        const float* __restrict__ bias, int relu,
                        float* __restrict__ out, int N) {
    int node = blockIdx.x * 8 + (threadIdx.x >> 5);
    int lane = threadIdx.x & 31;
    if (node >= N) return;
    float acc = 0.f;
    int e0 = rowoff[node], e1 = rowend[node];
    for (int e = e0; e < e1; e++) {
        EdgeRec r = edges[e];
        acc = fmaf(r.w, u[(size_t)r.src * 32 + lane], acc);
    }
    float dv = dis[node];
    acc = fmaf(dv * dv, u[(size_t)node * 32 + lane], acc);
    if (bias) acc += bias[lane];
    if (relu) acc = fmaxf(acc, 0.f);
    out[(size_t)node * 32 + lane] = acc;
}

// small widths (2,3,8): thread per node
template <int W>
__global__ void k_agg_t(const float* __restrict__ u, const EdgeRec* __restrict__ edges,
                        const int* __restrict__ rowoff, const int* __restrict__ rowend,
                        const float* __restrict__ dis,
                        const float* __restrict__ bias, int relu,
                        float* __restrict__ out, int N) {
    int node = blockIdx.x * blockDim.x + threadIdx.x;
    if (node >= N) return;
    float acc[W];
#pragma unroll
    for (int k = 0; k < W; k++) acc[k] = 0.f;
    int e0 = rowoff[node], e1 = rowend[node];
    for (int e = e0; e < e1; e++) {
        EdgeRec r = edges[e];
        const float* up = u + (size_t)r.src * W;
#pragma unroll
        for (int k = 0; k < W; k++) acc[k] = fmaf(r.w, __ldg(up + k), acc[k]);
    }
    float dv = dis[node];
    float sw = dv * dv;
    const float* us = u + (size_t)node * W;
#pragma unroll
    for (int k = 0; k < W; k++) acc[k] = fmaf(sw, us[k], acc[k]);
    if (bias) {
#pragma unroll
        for (int k = 0; k < W; k++) acc[k] += bias[k];
    }
    if (relu) {
#pragma unroll
        for (int k = 0; k < W; k++) acc[k] = fmaxf(acc[k], 0.f);
    }
#pragma unroll
    for (int k = 0; k < W; k++) out[(size_t)node * W + k] = acc[k];
}

// =============== dense kernels ===============

// projection: t = relu(aggx @ Wp + bp), fp32 + fp16 mirror
__global__ void k_proj(const float* __restrict__ aggx, const float* __restrict__ Wp,
                       const float* __restrict__ bp, float* __restrict__ t,
                       __half* __restrict__ t16, int N) {
    int node = blockIdx.x * 4 + (threadIdx.x >> 6);
    int j = threadIdx.x & 63;
    if (node >= N) return;
    float a0 = aggx[node * 3], a1 = aggx[node * 3 + 1], a2 = aggx[node * 3 + 2];
    float acc = bp[j];
    acc = fmaf(a0, Wp[j], acc);
    acc = fmaf(a1, Wp[64 + j], acc);
    acc = fmaf(a2, Wp[128 + j], acc);
    acc = fmaxf(acc, 0.f);
    t[(size_t)node * 64 + j] = acc;
    t16[(size_t)node * 64 + j] = __float2half_rn(acc);
}

// tensor-core matmul: C[N,64] = A16[N,64] @ W16[64,64]  (fp16 in, fp32 acc)
// RECALL: epilogue adds aggx@Wx + br, writes fp32 out + fp16 mirror.
// else: writes fp16 mirror only.
template <int RECALL>
__global__ void __launch_bounds__(256) k_mmTC(
    const __half* __restrict__ A16, const __half* __restrict__ W16,
    const float* __restrict__ Wx, const float* __restrict__ brv,
    const float* __restrict__ aggx,
    float* __restrict__ out32, __half* __restrict__ out16, int N) {
    __shared__ __align__(32) __half Ws[64 * 64];
    __shared__ __align__(32) float stage[128 * 64];
    int tid = threadIdx.x;
    int warp = tid >> 5;
    int row0 = blockIdx.x * 128;

    {
        const uint4* src = (const uint4*)W16;
        uint4* dst = (uint4*)Ws;
        for (int i = tid; i < 512; i += 256) dst[i] = src[i];
    }
    __syncthreads();

    wmma::fragment<wmma::accumulator, 16, 16, 16, float> acc[4];
#pragma unroll
    for (int nt = 0; nt < 4; nt++) wmma::fill_fragment(acc[nt], 0.f);

    const __half* Abase = A16 + (size_t)(row0 + warp * 16) * 64;
#pragma unroll
    for (int kt = 0; kt < 4; kt++) {
        wmma::fragment<wmma::matrix_a, 16, 16, 16, __half, wmma::row_major> af;
        wmma::load_matrix_sync(af, Abase + kt * 16, 64);
#pragma unroll
        for (int nt = 0; nt < 4; nt++) {
            wmma::fragment<wmma::matrix_b, 16, 16, 16, __half, wmma::row_major> bf;
            wmma::load_matrix_sync(bf, Ws + kt * 16 * 64 + nt * 16, 64);
            wmma::mma_sync(acc[nt], af, bf, acc[nt]);
        }
    }
#pragma unroll
    for (int nt = 0; nt < 4; nt++)
        wmma::store_matrix_sync(stage + warp * 16 * 64 + nt * 16, acc[nt], 64,
                                wmma::mem_row_major);
    __syncthreads();

    // epilogue: i indexes (row, 4-col quad)
    for (int i = tid; i < 128 * 16; i += 256) {
        int row = i >> 4;
        int q = i & 15;
        int grow = row0 + row;
        if (grow >= N) break;
        float4 c = ((const float4*)stage)[i];
        if (RECALL) {
            float a0 = aggx[grow * 3], a1 = aggx[grow * 3 + 1], a2 = aggx[grow * 3 + 2];
            int col = q * 4;
#pragma unroll
            for (int jj = 0; jj < 4; jj++) {
                float add = fmaf(a0, Wx[col + jj],
                             fmaf(a1, Wx[64 + col + jj],
                              fmaf(a2, Wx[128 + col + jj], brv[col + jj])));
                (&c.x)[jj] += add;
            }
            ((float4*)out32)[(size_t)grow * 16 + q] = c;
        }
        uint2 m;
        m.x = f2h(c.x, c.y);
        m.y = f2h(c.z, c.w);
        ((uint2*)out16)[(size_t)grow * 16 + q] = m;
    }
}

// small head matmuls: warp per node
template <int FIN, int FOUT>
__global__ void k_mm_small(const float* __restrict__ A, const float* __restrict__ W,
                           float* __restrict__ C, int N) {
    __shared__ float Ws[FIN * FOUT + 32];
    int tid = threadIdx.x;
    for (int i = tid; i < FIN * FOUT; i += blockDim.x) Ws[i] = W[i];
    for (int i = FIN * FOUT + tid; i < FIN * FOUT + 32; i += blockDim.x) Ws[i] = 0.f;
    __syncthreads();
    int node = blockIdx.x * 4 + (tid >> 5);
    int j = tid & 31;
    if (node >= N) return;
    float acc = 0.f;
    const float* a = A + (size_t)node * FIN;
#pragma unroll
    for (int k = 0; k < FIN; k++) {
        float av = __ldg(a + k);
        acc = fmaf(av, Ws[k * FOUT + j], acc);
    }
    if (j < FOUT) C[(size_t)node * FOUT + j] = acc;
}

// =============== host launch ===============

extern "C" void kernel_launch(void* const* d_in, const int* in_sizes, int n_in,
                              void* d_out, int out_size) {
    const float* x   = (const float*)d_in[0];
    const float* Wp  = (const float*)d_in[1];
    const float* bp  = (const float*)d_in[2];
    const float* Wr  = (const float*)d_in[3];
    const float* br  = (const float*)d_in[4];
    const float* W11 = (const float*)d_in[5];
    const float* b11 = (const float*)d_in[6];
    const float* W12 = (const float*)d_in[7];
    const float* b12 = (const float*)d_in[8];
    const float* W21 = (const float*)d_in[9];
    const float* b21 = (const float*)d_in[10];
    const float* W22 = (const float*)d_in[11];
    const float* b22 = (const float*)d_in[12];
    const float* Wh1 = (const float*)d_in[13];
    const float* bh1 = (const float*)d_in[14];
    const float* Wh2 = (const float*)d_in[15];
    const float* bh2 = (const float*)d_in[16];
    const float* Wh3 = (const float*)d_in[17];
    const float* bh3 = (const float*)d_in[18];
    const int*   ei  = (const int*)d_in[19];

    int N = in_sizes[0] / 3;
    int E = in_sizes[19] / 2;
    const int* esrc = ei;
    const int* edst = ei + E;

    int *counts, *cursor, *rowoff, *rowend, *total;
    float *dis, *aggx;
    EdgeRec* edges;
    float4 *t4, *u4, *v4;
    uint4 *t16p, *u16p, *v16p, *w16p;
    cudaGetSymbolAddress((void**)&counts, g_counts);
    cudaGetSymbolAddress((void**)&cursor, g_cursor);
    cudaGetSymbolAddress((void**)&rowoff, g_rowoff);
    cudaGetSymbolAddress((void**)&rowend, g_rowend);
    cudaGetSymbolAddress((void**)&total, g_total);
    cudaGetSymbolAddress((void**)&dis, g_dis);
    cudaGetSymbolAddress((void**)&edges, g_edges);
    cudaGetSymbolAddress((void**)&aggx, g_aggx);
    cudaGetSymbolAddress((void**)&t4, g_t);
    cudaGetSymbolAddress((void**)&u4, g_u);
    cudaGetSymbolAddress((void**)&v4, g_v);
    cudaGetSymbolAddress((void**)&t16p, g_t16);
    cudaGetSymbolAddress((void**)&u16p, g_u16);
    cudaGetSymbolAddress((void**)&v16p, g_v16);
    cudaGetSymbolAddress((void**)&w16p, g_w16);
    float* t = (float*)t4;
    float* u = (float*)u4;
    float* v = (float*)v4;
    __half* t16 = (__half*)t16p;
    __half* u16 = (__half*)u16p;
    __half* v16 = (__half*)v16p;
    __half* w16 = (__half*)w16p;
    __half* Wr16  = w16;
    __half* W11_16 = w16 + 4096;
    __half* W12_16 = w16 + 2 * 4096;
    __half* W21_16 = w16 + 3 * 4096;
    __half* W22_16 = w16 + 4 * 4096;

    int nbE = (E + 255) / 256;
    int nbN = (N + 255) / 256;
    int nbWarp = (N + 7) / 8;       // 8 nodes per 256-thread block
    int nbAgg = (N + 15) / 16;      // 16 nodes per 256-thread block (half-warp)
    int nbTC = (N + 127) / 128;     // tensor-core mm tiles
    int nbW4 = (N + 3) / 4;

    // ---- graph setup ----
    cudaMemsetAsync(counts, 0, (size_t)N * sizeof(int), 0);
    cudaMemsetAsync(cursor, 0, (size_t)N * sizeof(int), 0);
    cudaMemsetAsync(total, 0, 4 * sizeof(int), 0);
    k_cvtW<<<16, 256>>>(Wr, W11, W12, W21, W22, w16);
    k_count<<<nbE, 256>>>(edst, E, counts);
    k_dis<<<nbN, 256>>>(counts, dis, N);
    k_alloc<<<nbN, 256>>>(counts, rowoff, rowend, total, N);
    k_fill<<<nbE, 256>>>(esrc, edst, E, rowoff, cursor, dis, edges);

    // ---- loop-invariant: agg(x) and projection ----
    k_agg_t<3><<<nbN, 256>>>(x, edges, rowoff, rowend, dis, nullptr, 0, aggx, N);
    k_proj<<<nbW4, 256>>>(aggx, Wp, bp, t, t16, N);

    const float* Wrx = Wr + 64 * 64;  // rows 64..66 of Wr (x part)

    // ---- iterations ----
    for (int it = 0; it < ITERS; it++) {
        // recall: v16 = agg(t16); t,t16 = v16@Wr_t + aggx@Wr_x + br
        k_aggv<0, 0, 0><<<nbAgg, 256>>>((uint2*)t16, edges, rowoff, rowend, dis,
                                        nullptr, nullptr, nullptr, (uint2*)v16, N);
        k_mmTC<1><<<nbTC, 256>>>(v16, Wr16, Wrx, br, aggx, t, t16, N);
        // block 1
        k_mmTC<0><<<nbTC, 256>>>(t16, W11_16, nullptr, nullptr, nullptr,
                                 nullptr, u16, N);
        k_aggv<1, 0, 0><<<nbAgg, 256>>>((uint2*)u16, edges, rowoff, rowend, dis,
                                        b11, nullptr, nullptr, (uint2*)v16, N);
        k_mmTC<0><<<nbTC, 256>>>(v16, W12_16, nullptr, nullptr, nullptr,
                                 nullptr, u16, N);
        k_aggv<1, 1, 1><<<nbAgg, 256>>>((uint2*)u16, edges, rowoff, rowend, dis,
                                        b12, t, t, (uint2*)t16, N);
        // block 2
        k_mmTC<0><<<nbTC, 256>>>(t16, W21_16, nullptr, nullptr, nullptr,
                                 nullptr, u16, N);
        k_aggv<1, 0, 0><<<nbAgg, 256>>>((uint2*)u16, edges, rowoff, rowend, dis,
                                        b21, nullptr, nullptr, (uint2*)v16, N);
        k_mmTC<0><<<nbTC, 256>>>(v16, W22_16, nullptr, nullptr, nullptr,
                                 nullptr, u16, N);
        k_aggv<1, 1, 1><<<nbAgg, 256>>>((uint2*)u16, edges, rowoff, rowend, dis,
                                        b22, t, t, (uint2*)t16, N);
    }

    // ---- head (fp32 throughout) ----
    k_mm_small<64, 32><<<nbW4, 128>>>(t, Wh1, u, N);
    k_agg32<<<nbWarp, 256>>>(u, edges, rowoff, rowend, dis, bh1, 1, v, N);
    k_mm_small<32, 8><<<nbW4, 128>>>(v, Wh2, u, N);
    k_agg_t<8><<<nbN, 256>>>(u, edges, rowoff, rowend, dis, bh2, 1, v, N);
    k_mm_small<8, 2><<<nbW4, 128>>>(v, Wh3, u, N);
    k_agg_t<2><<<nbN, 256>>>(u, edges, rowoff, rowend, dis, bh3, 0, (float*)d_out, N);
}